// round 6
// baseline (speedup 1.0000x reference)
#include <cuda_runtime.h>
#include <math.h>

#define NB 8
#define NL 12
#define NS 1023
#define NS1 1024
#define NE 768
#define NH 12
#define ND 64
#define NV 50257
#define NFF 3072
#define NE3 2304
#define GRID 148
#define TPB 768

// ---------------- device scratch ----------------------------------------------
__device__ __align__(16) float g_states[NB*NE];
__device__ __align__(16) float g_qkv[NB*NE3];
__device__ __align__(16) float g_ctx[NB*NE];
__device__ __align__(16) float g_hbuf[NB*NFF];
__device__ __align__(16) float g_scores[NB*NH*NS1];
__device__ __align__(16) float g_logits[NB*NV];
__device__ int g_lp[NB];
__device__ unsigned long long g_vmax[NB];
__device__ float g_vsum[NB];
__device__ volatile unsigned g_gen;
__device__ unsigned g_cnt;

// ---------------- grid-wide barrier (all 148 blocks co-resident) ---------------
__device__ __forceinline__ void gsync(){
    __syncthreads();
    if (threadIdx.x == 0){
        unsigned gen = *(volatile unsigned*)&g_gen;
        unsigned prev;
        asm volatile("atom.add.acq_rel.gpu.u32 %0, [%1], 1;"
                     : "=r"(prev) : "l"(&g_cnt) : "memory");
        if (prev == GRID - 1){
            g_cnt = 0;
            asm volatile("st.release.gpu.u32 [%0], %1;" :: "l"((unsigned*)&g_gen), "r"(gen+1) : "memory");
        } else {
            unsigned cur;
            do {
                __nanosleep(64);
                asm volatile("ld.acquire.gpu.u32 %0, [%1];" : "=r"(cur) : "l"((unsigned*)&g_gen) : "memory");
            } while (cur == gen);
        }
    }
    __syncthreads();
}

// ---------------- redundant per-block layernorm of g_states -> dst[8*768] ------
__device__ __forceinline__ void block_ln(const float* __restrict__ w,
                                         const float* __restrict__ bb, float* dst){
    int warp = threadIdx.x >> 5, lane = threadIdx.x & 31;
    if (warp < 8){
        const float* x = g_states + warp*NE;
        float s = 0.f;
        for (int i = lane; i < NE; i += 32) s += x[i];
        #pragma unroll
        for (int o = 16; o; o >>= 1) s += __shfl_xor_sync(0xffffffffu, s, o);
        float mean = s*(1.0f/NE);
        float v = 0.f;
        for (int i = lane; i < NE; i += 32){ float d = x[i]-mean; v += d*d; }
        #pragma unroll
        for (int o = 16; o; o >>= 1) v += __shfl_xor_sync(0xffffffffu, v, o);
        float rs = rsqrtf(v*(1.0f/NE) + 1e-5f);
        for (int i = lane; i < NE; i += 32)
            dst[warp*NE + i] = (x[i]-mean)*rs*w[i] + bb[i];
    }
}

__device__ __forceinline__ unsigned ordf(float f){
    unsigned u = __float_as_uint(f);
    return (u & 0x80000000u) ? ~u : (u | 0x80000000u);
}
__device__ __forceinline__ float unordf(unsigned k){
    unsigned u = (k & 0x80000000u) ? (k & 0x7fffffffu) : ~k;
    return __uint_as_float(u);
}

// ================================ MEGAKERNEL ===================================
__global__ void __launch_bounds__(TPB, 1)
mega_kernel(const int* __restrict__ ids, const int* __restrict__ mask,
            const float* __restrict__ kv, const float* __restrict__ wte,
            const float* __restrict__ wpe,
            const float* __restrict__ ln1w, const float* __restrict__ ln1b,
            const float* __restrict__ caw,  const float* __restrict__ cab,
            const float* __restrict__ ab,
            const float* __restrict__ cpw,  const float* __restrict__ cpb,
            const float* __restrict__ ln2w, const float* __restrict__ ln2b,
            const float* __restrict__ fcw,  const float* __restrict__ fcb,
            const float* __restrict__ prw,  const float* __restrict__ prb,
            const float* __restrict__ lnfw, const float* __restrict__ lnfb,
            float* nkv, float* probs, float* chosen_f, int* chosen_i){
    __shared__ __align__(16) float sh[6400];
    int bid = blockIdx.x, tid = threadIdx.x;
    int warp = tid >> 5, lane = tid & 31;
    int jt = tid % 192, eg = tid / 192;   // GEMV thread groups

    // ---------- phase E: last-position + embedding; zero qkv, ctx --------------
    if (bid < NB){
        int b = bid;
        __shared__ int s_lp;
        if (warp == 0){
            int best = -1;
            for (int s = lane; s < NS1; s += 32)
                if (mask[b*NS1 + s] != 0) best = (s > best) ? s : best;
            #pragma unroll
            for (int o = 16; o; o >>= 1){
                int ot = __shfl_xor_sync(0xffffffffu, best, o);
                best = (ot > best) ? ot : best;
            }
            if (lane == 0){ s_lp = best; g_lp[b] = best; }
        }
        __syncthreads();
        int lp = s_lp, tok = ids[b*NS1 + lp];
        for (int e = tid; e < NE; e += TPB)
            g_states[b*NE + e] = wte[(size_t)tok*NE + e] + wpe[(size_t)lp*NE + e];
    }
    for (int i = bid*TPB + tid; i < NB*NE3; i += GRID*TPB) g_qkv[i] = 0.f;
    for (int i = bid*TPB + tid; i < NB*NE;  i += GRID*TPB) g_ctx[i] = 0.f;
    gsync();

    // =========================== layers ========================================
    for (int l = 0; l < NL; l++){
        const float* cawl = caw + (size_t)l*NE*NE3;
        const float* cpwl = cpw + (size_t)l*NE*NE;
        const float* fcwl = fcw + (size_t)l*NE*NFF;
        const float* prwl = prw + (size_t)l*NFF*NE;
        const float* abl  = ab  + (size_t)l*NS1;

        // ---- P1: ln1 (redundant) + qkv GEMV; zero hbuf ------------------------
        block_ln(ln1w + l*NE, ln1b + l*NE, sh);
        for (int i = bid*TPB + tid; i < NB*NFF; i += GRID*TPB) g_hbuf[i] = 0.f;
        __syncthreads();
        for (int t = bid; t < 72; t += GRID){
            int eb = t / 3, jb = t % 3;
            int e0 = eb*32 + eg*8;
            int j = jb*768 + jt*4;
            float4 acc[8];
            #pragma unroll
            for (int b2 = 0; b2 < 8; b2++) acc[b2] = make_float4(0.f,0.f,0.f,0.f);
            const float* Wp = cawl + (size_t)e0*NE3 + j;
            #pragma unroll
            for (int e = 0; e < 8; e++){
                float4 w4 = *(const float4*)(Wp + (size_t)e*NE3);
                #pragma unroll
                for (int b2 = 0; b2 < 8; b2++){
                    float xv = sh[b2*NE + e0 + e];
                    acc[b2].x = fmaf(xv,w4.x,acc[b2].x); acc[b2].y = fmaf(xv,w4.y,acc[b2].y);
                    acc[b2].z = fmaf(xv,w4.z,acc[b2].z); acc[b2].w = fmaf(xv,w4.w,acc[b2].w);
                }
            }
            if (e0 == 0){
                float4 bv = *(const float4*)(cab + (size_t)l*NE3 + j);
                #pragma unroll
                for (int b2 = 0; b2 < 8; b2++){
                    acc[b2].x += bv.x; acc[b2].y += bv.y; acc[b2].z += bv.z; acc[b2].w += bv.w;
                }
            }
            #pragma unroll
            for (int b2 = 0; b2 < 8; b2++){
                float* p = g_qkv + (size_t)b2*NE3 + j;
                atomicAdd(p+0,acc[b2].x); atomicAdd(p+1,acc[b2].y);
                atomicAdd(p+2,acc[b2].z); atomicAdd(p+3,acc[b2].w);
            }
        }
        gsync();

        // ---- attn_kv: K/V copy into new_kv + scores (warp per row, 24 warps) ---
        for (int i = tid; i < NB*NE; i += TPB){
            int b = i / NE, e = i - b*NE;
            sh[i] = g_qkv[b*NE3 + e];
        }
        __syncthreads();
        {
            const float* kc0 = kv + (size_t)(l*2+0)*NB*(size_t)NS*NE;
            const float* vc0 = kv + (size_t)(l*2+1)*NB*(size_t)NS*NE;
            float* ko0 = nkv ? nkv + (size_t)(l*2+0)*NB*(size_t)NS1*NE : nullptr;
            float* vo0 = nkv ? nkv + (size_t)(l*2+1)*NB*(size_t)NS1*NE : nullptr;
            for (int r = bid*24 + warp; r < NB*NS1; r += GRID*24){
                int b = r >> 10, s = r & (NS1-1);
                int lp = g_lp[b];
                bool isnew = (s == lp);
                bool iszero = (s == NS) && !isnew;
                const float* ksrc = isnew ? (g_qkv + b*NE3 + NE)   : (kc0 + ((size_t)b*NS + s)*NE);
                const float* vsrc = isnew ? (g_qkv + b*NE3 + 2*NE) : (vc0 + ((size_t)b*NS + s)*NE);
                const float* qs = sh + b*NE;
                float4 k4[6], v4[6];
                #pragma unroll
                for (int c = 0; c < 6; c++){
                    int e = c*128 + lane*4;
                    if (iszero){ k4[c] = make_float4(0.f,0.f,0.f,0.f); v4[c] = k4[c]; }
                    else { k4[c] = *(const float4*)(ksrc + e); v4[c] = *(const float4*)(vsrc + e); }
                }
                if (ko0){
                    #pragma unroll
                    for (int c = 0; c < 6; c++){
                        int e = c*128 + lane*4;
                        *(float4*)(ko0 + ((size_t)b*NS1 + s)*NE + e) = k4[c];
                        *(float4*)(vo0 + ((size_t)b*NS1 + s)*NE + e) = v4[c];
                    }
                }
                float part[6];
                #pragma unroll
                for (int c = 0; c < 6; c++){
                    int e = c*128 + lane*4;
                    part[c] = k4[c].x*qs[e] + k4[c].y*qs[e+1] + k4[c].z*qs[e+2] + k4[c].w*qs[e+3];
                }
                #pragma unroll
                for (int c = 0; c < 6; c++){
                    float p = part[c];
                    p += __shfl_xor_sync(0xffffffffu, p, 8);
                    p += __shfl_xor_sync(0xffffffffu, p, 4);
                    p += __shfl_xor_sync(0xffffffffu, p, 2);
                    p += __shfl_xor_sync(0xffffffffu, p, 1);
                    part[c] = p;
                }
                if ((lane & 15) == 0){
                    int hb = lane >> 4;
                    bool msk = (mask[b*NS1 + s] == 0);
                    float abv = abl[s];
                    #pragma unroll
                    for (int c = 0; c < 6; c++)
                        g_scores[((size_t)b*NH + 2*c + hb)*NS1 + s] = msk ? -1e9f : (part[c]*0.125f + abv);
                }
            }
        }
        gsync();

        // ---- attn_sv: redundant softmax + weighted V --------------------------
        {
            float* sm   = sh;           // [1024]
            float* red  = sh + 1024;    // [24]
            float* cacc = sh + 1056;    // [512]
            for (int t = bid; t < NB*NH*2; t += GRID){
                int b = t / (NH*2), rem = t - b*(NH*2);
                int h = rem >> 1, ck = rem & 1;
                __syncthreads();
                const float* sr = g_scores + ((size_t)b*NH + h)*NS1;
                float a0 = sr[tid];
                float a1 = (tid < 256) ? sr[768 + tid] : -1e30f;
                float m = fmaxf(a0, a1);
                #pragma unroll
                for (int o = 16; o; o >>= 1) m = fmaxf(m, __shfl_xor_sync(0xffffffffu, m, o));
                if (lane == 0) red[warp] = m;
                __syncthreads();
                m = red[0];
                #pragma unroll
                for (int w2 = 1; w2 < 24; w2++) m = fmaxf(m, red[w2]);
                float e0v = expf(a0 - m);
                float e1v = (tid < 256) ? expf(a1 - m) : 0.f;
                float ssum = e0v + e1v;
                #pragma unroll
                for (int o = 16; o; o >>= 1) ssum += __shfl_xor_sync(0xffffffffu, ssum, o);
                __syncthreads();
                if (lane == 0) red[warp] = ssum;
                __syncthreads();
                float tot = red[0];
                #pragma unroll
                for (int w2 = 1; w2 < 24; w2++) tot += red[w2];
                float inv = 1.0f/tot;
                sm[tid] = e0v*inv;
                if (tid < 256) sm[768 + tid] = e1v*inv;
                __syncthreads();
                float acc = 0.f;
                int col = tid & 63, rp = (tid >> 6) & 7;
                if (tid < 512){
                    if (nkv){
                        const float* vo = nkv + (size_t)(l*2+1)*NB*(size_t)NS1*NE
                                        + (size_t)b*NS1*NE + h*ND + col;
                        #pragma unroll 8
                        for (int i = 0; i < 64; i++){
                            int s = ck*512 + i*8 + rp;
                            acc = fmaf(sm[s], vo[(size_t)s*NE], acc);
                        }
                    } else {
                        int lp = g_lp[b];
                        const float* vc = kv + (size_t)(l*2+1)*NB*(size_t)NS*NE + (size_t)b*NS*NE;
                        for (int i = 0; i < 64; i++){
                            int s = ck*512 + i*8 + rp;
                            float vv;
                            if (s == lp) vv = g_qkv[b*NE3 + 2*NE + h*ND + col];
                            else if (s == NS) vv = 0.f;
                            else vv = vc[(size_t)s*NE + h*ND + col];
                            acc = fmaf(sm[s], vv, acc);
                        }
                    }
                    cacc[tid] = acc;
                }
                __syncthreads();
                if (tid < 64){
                    float r = cacc[tid];
                    #pragma unroll
                    for (int p2 = 1; p2 < 8; p2++) r += cacc[tid + p2*64];
                    atomicAdd(&g_ctx[b*NE + h*ND + tid], r);
                }
            }
        }
        gsync();

        // ---- cproj: states += ctx @ cpw + cpb; zero qkv -----------------------
        for (int i = bid*TPB + tid; i < NB*NE3; i += GRID*TPB) g_qkv[i] = 0.f;
        for (int t = bid; t < 24; t += GRID){
            __syncthreads();
            if (tid < 256){
                int b2 = tid >> 5, e = tid & 31;
                sh[tid] = g_ctx[b2*NE + t*32 + e];
            }
            __syncthreads();
            int e0g = eg*8;
            int j = jt*4;
            float4 acc[8];
            #pragma unroll
            for (int b2 = 0; b2 < 8; b2++) acc[b2] = make_float4(0.f,0.f,0.f,0.f);
            const float* Wp = cpwl + (size_t)(t*32 + e0g)*NE + j;
            #pragma unroll
            for (int e = 0; e < 8; e++){
                float4 w4 = *(const float4*)(Wp + (size_t)e*NE);
                #pragma unroll
                for (int b2 = 0; b2 < 8; b2++){
                    float xv = sh[b2*32 + e0g + e];
                    acc[b2].x = fmaf(xv,w4.x,acc[b2].x); acc[b2].y = fmaf(xv,w4.y,acc[b2].y);
                    acc[b2].z = fmaf(xv,w4.z,acc[b2].z); acc[b2].w = fmaf(xv,w4.w,acc[b2].w);
                }
            }
            if (t == 0 && eg == 0){
                float4 bv = *(const float4*)(cpb + (size_t)l*NE + j);
                #pragma unroll
                for (int b2 = 0; b2 < 8; b2++){
                    acc[b2].x += bv.x; acc[b2].y += bv.y; acc[b2].z += bv.z; acc[b2].w += bv.w;
                }
            }
            #pragma unroll
            for (int b2 = 0; b2 < 8; b2++){
                float* p = g_states + (size_t)b2*NE + j;
                atomicAdd(p+0,acc[b2].x); atomicAdd(p+1,acc[b2].y);
                atomicAdd(p+2,acc[b2].z); atomicAdd(p+3,acc[b2].w);
            }
        }
        gsync();

        // ---- fc: ln2 (redundant) + fc GEMV; zero ctx --------------------------
        block_ln(ln2w + l*NE, ln2b + l*NE, sh);
        for (int i = bid*TPB + tid; i < NB*NE; i += GRID*TPB) g_ctx[i] = 0.f;
        __syncthreads();
        for (int t = bid; t < 96; t += GRID){
            int eb = t % 24, jb = t / 24;
            int e0 = eb*32 + eg*8;
            int j = jb*768 + jt*4;
            float4 acc[8];
            #pragma unroll
            for (int b2 = 0; b2 < 8; b2++) acc[b2] = make_float4(0.f,0.f,0.f,0.f);
            const float* Wp = fcwl + (size_t)e0*NFF + j;
            #pragma unroll
            for (int e = 0; e < 8; e++){
                float4 w4 = *(const float4*)(Wp + (size_t)e*NFF);
                #pragma unroll
                for (int b2 = 0; b2 < 8; b2++){
                    float xv = sh[b2*NE + e0 + e];
                    acc[b2].x = fmaf(xv,w4.x,acc[b2].x); acc[b2].y = fmaf(xv,w4.y,acc[b2].y);
                    acc[b2].z = fmaf(xv,w4.z,acc[b2].z); acc[b2].w = fmaf(xv,w4.w,acc[b2].w);
                }
            }
            if (e0 == 0){
                float4 bv = *(const float4*)(fcb + (size_t)l*NFF + j);
                #pragma unroll
                for (int b2 = 0; b2 < 8; b2++){
                    acc[b2].x += bv.x; acc[b2].y += bv.y; acc[b2].z += bv.z; acc[b2].w += bv.w;
                }
            }
            #pragma unroll
            for (int b2 = 0; b2 < 8; b2++){
                float* p = g_hbuf + (size_t)b2*NFF + j;
                atomicAdd(p+0,acc[b2].x); atomicAdd(p+1,acc[b2].y);
                atomicAdd(p+2,acc[b2].z); atomicAdd(p+3,acc[b2].w);
            }
        }
        gsync();

        // ---- proj: states += gelu(hbuf) @ prw + prb ---------------------------
        for (int t = bid; t < 96; t += GRID){
            __syncthreads();
            if (tid < 256){
                int b2 = tid >> 5, e = tid & 31;
                float v = g_hbuf[b2*NFF + t*32 + e];
                sh[tid] = 0.5f*v*(1.0f + erff(v*0.70710678118654752f));
            }
            __syncthreads();
            int e0g = eg*8;
            int j = jt*4;
            float4 acc[8];
            #pragma unroll
            for (int b2 = 0; b2 < 8; b2++) acc[b2] = make_float4(0.f,0.f,0.f,0.f);
            const float* Wp = prwl + (size_t)(t*32 + e0g)*NE + j;
            #pragma unroll
            for (int e = 0; e < 8; e++){
                float4 w4 = *(const float4*)(Wp + (size_t)e*NE);
                #pragma unroll
                for (int b2 = 0; b2 < 8; b2++){
                    float xv = sh[b2*32 + e0g + e];
                    acc[b2].x = fmaf(xv,w4.x,acc[b2].x); acc[b2].y = fmaf(xv,w4.y,acc[b2].y);
                    acc[b2].z = fmaf(xv,w4.z,acc[b2].z); acc[b2].w = fmaf(xv,w4.w,acc[b2].w);
                }
            }
            if (t == 0 && eg == 0){
                float4 bv = *(const float4*)(prb + (size_t)l*NE + j);
                #pragma unroll
                for (int b2 = 0; b2 < 8; b2++){
                    acc[b2].x += bv.x; acc[b2].y += bv.y; acc[b2].z += bv.z; acc[b2].w += bv.w;
                }
            }
            #pragma unroll
            for (int b2 = 0; b2 < 8; b2++){
                float* p = g_states + (size_t)b2*NE + j;
                atomicAdd(p+0,acc[b2].x); atomicAdd(p+1,acc[b2].y);
                atomicAdd(p+2,acc[b2].z); atomicAdd(p+3,acc[b2].w);
            }
        }
        gsync();
    }

    // ---------- lm head --------------------------------------------------------
    block_ln(lnfw, lnfb, sh);
    if (bid == 0 && tid < NB){ g_vmax[tid] = 0ull; g_vsum[tid] = 0.f; }
    __syncthreads();
    for (int t = bid*24 + warp; t < (NV+1)/2; t += GRID*24){
        long long t0 = (long long)t*2;
        bool has1 = (t0 + 1 < NV);
        const float* r0 = wte + (size_t)t0*NE;
        const float* r1 = has1 ? wte + (size_t)(t0+1)*NE : r0;
        float acc[16];
        #pragma unroll
        for (int i = 0; i < 16; i++) acc[i] = 0.f;
        #pragma unroll
        for (int c = 0; c < 6; c++){
            int e = c*128 + lane*4;
            float4 w0 = *(const float4*)(r0 + e);
            float4 w1 = *(const float4*)(r1 + e);
            #pragma unroll
            for (int b2 = 0; b2 < 8; b2++){
                float4 x4 = *(const float4*)&sh[b2*NE + e];
                acc[b2]   = fmaf(w0.x,x4.x, fmaf(w0.y,x4.y, fmaf(w0.z,x4.z, fmaf(w0.w,x4.w, acc[b2]))));
                acc[8+b2] = fmaf(w1.x,x4.x, fmaf(w1.y,x4.y, fmaf(w1.z,x4.z, fmaf(w1.w,x4.w, acc[8+b2]))));
            }
        }
        #pragma unroll
        for (int i = 0; i < 16; i++){
            float p = acc[i];
            p += __shfl_xor_sync(0xffffffffu, p, 16);
            p += __shfl_xor_sync(0xffffffffu, p, 8);
            p += __shfl_xor_sync(0xffffffffu, p, 4);
            p += __shfl_xor_sync(0xffffffffu, p, 2);
            p += __shfl_xor_sync(0xffffffffu, p, 1);
            acc[i] = p;
        }
        if (lane < 8){
            g_logits[(size_t)lane*NV + t0] = acc[lane];
            if (has1) g_logits[(size_t)lane*NV + t0 + 1] = acc[8 + lane];
        }
    }
    gsync();

    // ---------- finish A: per-batch max/argmax ---------------------------------
    {
        unsigned long long* shu = (unsigned long long*)sh;
        for (int b = 0; b < NB; b++){
            const float* lg = g_logits + (size_t)b*NV;
            float bm = -1e30f; int bi = 0;
            for (int t = bid*TPB + tid; t < NV; t += GRID*TPB){
                float v = lg[t];
                if (v > bm){ bm = v; bi = t; }
            }
            unsigned long long key = ((unsigned long long)ordf(bm) << 32)
                                   | (unsigned long long)(0x7fffffffu - (unsigned)bi);
            #pragma unroll
            for (int o = 16; o; o >>= 1){
                unsigned long long ok = __shfl_xor_sync(0xffffffffu, key, o);
                if (ok > key) key = ok;
            }
            if (lane == 0) shu[warp] = key;
            __syncthreads();
            if (tid == 0){
                unsigned long long k = shu[0];
                #pragma unroll
                for (int w2 = 1; w2 < 24; w2++) if (shu[w2] > k) k = shu[w2];
                atomicMax(&g_vmax[b], k);
            }
            __syncthreads();
        }
    }
    gsync();

    // ---------- finish B: exp-sum (+ write unnormalized probs) -----------------
    for (int b = 0; b < NB; b++){
        float mx = unordf((unsigned)(g_vmax[b] >> 32));
        const float* lg = g_logits + (size_t)b*NV;
        float s = 0.f;
        for (int t = bid*TPB + tid; t < NV; t += GRID*TPB){
            float ev = expf(lg[t] - mx);
            s += ev;
            if (probs) probs[(size_t)b*NV + t] = ev;
        }
        #pragma unroll
        for (int o = 16; o; o >>= 1) s += __shfl_xor_sync(0xffffffffu, s, o);
        if (lane == 0) sh[warp] = s;
        __syncthreads();
        if (tid == 0){
            float tot = sh[0];
            #pragma unroll
            for (int w2 = 1; w2 < 24; w2++) tot += sh[w2];
            atomicAdd(&g_vsum[b], tot);
        }
        __syncthreads();
    }
    gsync();

    // ---------- finish C: normalize + chosen -----------------------------------
    if (probs){
        for (int b = 0; b < NB; b++){
            float inv = 1.0f/g_vsum[b];
            for (int t = bid*TPB + tid; t < NV; t += GRID*TPB)
                probs[(size_t)b*NV + t] *= inv;
        }
    }
    if (bid == 0 && tid < NB){
        int am = (int)(0x7fffffffu - (unsigned)(g_vmax[tid] & 0xffffffffu));
        if (chosen_f) chosen_f[tid] = (float)am;
        if (chosen_i) chosen_i[tid] = am;
    }
}

// ---------------- launch --------------------------------------------------------
extern "C" void kernel_launch(void* const* d_in, const int* in_sizes, int n_in,
                              void* d_out, int out_size){
    const int*   ids  = (const int*)  d_in[0];
    const int*   mask = (const int*)  d_in[1];
    const float* kv   = (const float*)d_in[2];
    const float* wte  = (const float*)d_in[3];
    const float* wpe  = (const float*)d_in[4];
    const float* ln1w = (const float*)d_in[5];
    const float* ln1b = (const float*)d_in[6];
    const float* caw  = (const float*)d_in[7];
    const float* cab  = (const float*)d_in[8];
    const float* ab   = (const float*)d_in[9];
    const float* cpw  = (const float*)d_in[10];
    const float* cpb  = (const float*)d_in[11];
    const float* ln2w = (const float*)d_in[12];
    const float* ln2b = (const float*)d_in[13];
    const float* fcw  = (const float*)d_in[14];
    const float* fcb  = (const float*)d_in[15];
    const float* prw  = (const float*)d_in[16];
    const float* prb  = (const float*)d_in[17];
    const float* lnfw = (const float*)d_in[18];
    const float* lnfb = (const float*)d_in[19];

    long long nkvN  = (long long)NL*2*NB*NS1*NE;
    long long fullN = (long long)NB + (long long)NB*NV + nkvN;
    float* outf = (float*)d_out;
    float* chosen_f = nullptr; int* chosen_i = nullptr;
    float* probs = nullptr; float* nkv = nullptr;
    long long osz = (long long)out_size;
    if (osz == fullN){ chosen_f = outf; probs = outf + NB; nkv = outf + NB + (long long)NB*NV; }
    else if (osz == nkvN){ nkv = outf; }
    else if (osz == (long long)NB*NV){ probs = outf; }
    else if (osz == (long long)NB){ chosen_i = (int*)d_out; }
    else if (osz == (long long)NB + (long long)NB*NV){ chosen_f = outf; probs = outf + NB; }
    else {
        chosen_f = outf;
        if (osz >= (long long)NB + (long long)NB*NV) probs = outf + NB;
        if (osz >= fullN) nkv = outf + NB + (long long)NB*NV;
    }

    mega_kernel<<<GRID, TPB>>>(ids, mask, kv, wte, wpe, ln1w, ln1b, caw, cab, ab,
                               cpw, cpb, ln2w, ln2b, fcw, fcb, prw, prb, lnfw, lnfb,
                               nkv, probs, chosen_f, chosen_i);
}

// round 7
// speedup vs baseline: 1.0186x; 1.0186x over previous
#include <cuda_runtime.h>
#include <math.h>

#define NB 8
#define NL 12
#define NS 1023
#define NS1 1024
#define NE 768
#define NH 12
#define ND 64
#define NV 50257
#define NFF 3072
#define NE3 2304
#define GRID 148
#define TPB 768

// ---------------- device scratch ----------------------------------------------
__device__ __align__(16) float g_states[NB*NE];
__device__ __align__(16) float g_qkv[NB*NE3];
__device__ __align__(16) float g_ctx[NB*NE];
__device__ __align__(16) float g_hbuf[NB*NFF];
__device__ __align__(16) float g_scores[NB*NH*NS1];
__device__ __align__(16) float g_logits[NB*NV];
__device__ int g_lp[NB];
__device__ unsigned long long g_vmax[NB];
__device__ float g_vsum[NB];
__device__ volatile unsigned g_gen;
__device__ unsigned g_cnt;

// ---------------- grid-wide barrier (all 148 blocks co-resident) ---------------
__device__ __forceinline__ void gsync(){
    __syncthreads();
    if (threadIdx.x == 0){
        unsigned gen = *(volatile unsigned*)&g_gen;
        unsigned prev;
        asm volatile("atom.add.acq_rel.gpu.u32 %0, [%1], 1;"
                     : "=r"(prev) : "l"(&g_cnt) : "memory");
        if (prev == GRID - 1){
            g_cnt = 0;
            asm volatile("st.release.gpu.u32 [%0], %1;" :: "l"((unsigned*)&g_gen), "r"(gen+1) : "memory");
        } else {
            unsigned cur;
            do {
                __nanosleep(64);
                asm volatile("ld.acquire.gpu.u32 %0, [%1];" : "=r"(cur) : "l"((unsigned*)&g_gen) : "memory");
            } while (cur == gen);
        }
    }
    __syncthreads();
}

// ---------------- redundant per-block layernorm of g_states -> dst[8*768] ------
__device__ __forceinline__ void block_ln(const float* __restrict__ w,
                                         const float* __restrict__ bb, float* dst){
    int warp = threadIdx.x >> 5, lane = threadIdx.x & 31;
    if (warp < 8){
        const float* x = g_states + warp*NE;
        float s = 0.f;
        for (int i = lane; i < NE; i += 32) s += x[i];
        #pragma unroll
        for (int o = 16; o; o >>= 1) s += __shfl_xor_sync(0xffffffffu, s, o);
        float mean = s*(1.0f/NE);
        float v = 0.f;
        for (int i = lane; i < NE; i += 32){ float d = x[i]-mean; v += d*d; }
        #pragma unroll
        for (int o = 16; o; o >>= 1) v += __shfl_xor_sync(0xffffffffu, v, o);
        float rs = rsqrtf(v*(1.0f/NE) + 1e-5f);
        for (int i = lane; i < NE; i += 32)
            dst[warp*NE + i] = (x[i]-mean)*rs*w[i] + bb[i];
    }
}

__device__ __forceinline__ unsigned ordf(float f){
    unsigned u = __float_as_uint(f);
    return (u & 0x80000000u) ? ~u : (u | 0x80000000u);
}
__device__ __forceinline__ float unordf(unsigned k){
    unsigned u = (k & 0x80000000u) ? (k & 0x7fffffffu) : ~k;
    return __uint_as_float(u);
}

// ================================ MEGAKERNEL ===================================
__global__ void __launch_bounds__(TPB, 1)
mega_kernel(const int* __restrict__ ids, const int* __restrict__ mask,
            const float* __restrict__ kv, const float* __restrict__ wte,
            const float* __restrict__ wpe,
            const float* __restrict__ ln1w, const float* __restrict__ ln1b,
            const float* __restrict__ caw,  const float* __restrict__ cab,
            const float* __restrict__ ab,
            const float* __restrict__ cpw,  const float* __restrict__ cpb,
            const float* __restrict__ ln2w, const float* __restrict__ ln2b,
            const float* __restrict__ fcw,  const float* __restrict__ fcb,
            const float* __restrict__ prw,  const float* __restrict__ prb,
            const float* __restrict__ lnfw, const float* __restrict__ lnfb,
            float* nkv, float* probs, float* chosen_f, int* chosen_i){
    __shared__ __align__(16) float sh[6400];
    int bid = blockIdx.x, tid = threadIdx.x;
    int warp = tid >> 5, lane = tid & 31;
    int jt = tid % 192, eg = tid / 192;   // GEMV thread groups

    // ---------- phase E: last-position + embedding; zero qkv, ctx --------------
    if (bid < NB){
        int b = bid;
        __shared__ int s_lp;
        if (warp == 0){
            int best = -1;
            for (int s = lane; s < NS1; s += 32)
                if (mask[b*NS1 + s] != 0) best = (s > best) ? s : best;
            #pragma unroll
            for (int o = 16; o; o >>= 1){
                int ot = __shfl_xor_sync(0xffffffffu, best, o);
                best = (ot > best) ? ot : best;
            }
            if (lane == 0){ s_lp = best; g_lp[b] = best; }
        }
        __syncthreads();
        int lp = s_lp, tok = ids[b*NS1 + lp];
        for (int e = tid; e < NE; e += TPB)
            g_states[b*NE + e] = wte[(size_t)tok*NE + e] + wpe[(size_t)lp*NE + e];
    }
    for (int i = bid*TPB + tid; i < NB*NE3; i += GRID*TPB) g_qkv[i] = 0.f;
    for (int i = bid*TPB + tid; i < NB*NE;  i += GRID*TPB) g_ctx[i] = 0.f;
    gsync();

    // =========================== layers ========================================
    for (int l = 0; l < NL; l++){
        const float* cawl = caw + (size_t)l*NE*NE3;
        const float* cpwl = cpw + (size_t)l*NE*NE;
        const float* fcwl = fcw + (size_t)l*NE*NFF;
        const float* prwl = prw + (size_t)l*NFF*NE;
        const float* abl  = ab  + (size_t)l*NS1;

        // ---- P1: ln1 (redundant) + qkv GEMV; zero hbuf ------------------------
        block_ln(ln1w + l*NE, ln1b + l*NE, sh);
        for (int i = bid*TPB + tid; i < NB*NFF; i += GRID*TPB) g_hbuf[i] = 0.f;
        __syncthreads();
        for (int t = bid; t < 72; t += GRID){
            int eb = t / 3, jb = t % 3;
            int e0 = eb*32 + eg*8;
            int j = jb*768 + jt*4;
            float4 acc[8];
            #pragma unroll
            for (int b2 = 0; b2 < 8; b2++) acc[b2] = make_float4(0.f,0.f,0.f,0.f);
            const float* Wp = cawl + (size_t)e0*NE3 + j;
            #pragma unroll
            for (int e = 0; e < 8; e++){
                float4 w4 = *(const float4*)(Wp + (size_t)e*NE3);
                #pragma unroll
                for (int b2 = 0; b2 < 8; b2++){
                    float xv = sh[b2*NE + e0 + e];
                    acc[b2].x = fmaf(xv,w4.x,acc[b2].x); acc[b2].y = fmaf(xv,w4.y,acc[b2].y);
                    acc[b2].z = fmaf(xv,w4.z,acc[b2].z); acc[b2].w = fmaf(xv,w4.w,acc[b2].w);
                }
            }
            if (e0 == 0){
                float4 bv = *(const float4*)(cab + (size_t)l*NE3 + j);
                #pragma unroll
                for (int b2 = 0; b2 < 8; b2++){
                    acc[b2].x += bv.x; acc[b2].y += bv.y; acc[b2].z += bv.z; acc[b2].w += bv.w;
                }
            }
            #pragma unroll
            for (int b2 = 0; b2 < 8; b2++){
                float* p = g_qkv + (size_t)b2*NE3 + j;
                atomicAdd(p+0,acc[b2].x); atomicAdd(p+1,acc[b2].y);
                atomicAdd(p+2,acc[b2].z); atomicAdd(p+3,acc[b2].w);
            }
        }
        gsync();

        // ---- attn_kv: K/V copy into new_kv + scores (warp per row, 24 warps) ---
        for (int i = tid; i < NB*NE; i += TPB){
            int b = i / NE, e = i - b*NE;
            sh[i] = g_qkv[b*NE3 + e];
        }
        __syncthreads();
        {
            const float* kc0 = kv + (size_t)(l*2+0)*NB*(size_t)NS*NE;
            const float* vc0 = kv + (size_t)(l*2+1)*NB*(size_t)NS*NE;
            float* ko0 = nkv ? nkv + (size_t)(l*2+0)*NB*(size_t)NS1*NE : nullptr;
            float* vo0 = nkv ? nkv + (size_t)(l*2+1)*NB*(size_t)NS1*NE : nullptr;
            for (int r = bid*24 + warp; r < NB*NS1; r += GRID*24){
                int b = r >> 10, s = r & (NS1-1);
                int lp = g_lp[b];
                bool isnew = (s == lp);
                bool iszero = (s == NS) && !isnew;
                const float* ksrc = isnew ? (g_qkv + b*NE3 + NE)   : (kc0 + ((size_t)b*NS + s)*NE);
                const float* vsrc = isnew ? (g_qkv + b*NE3 + 2*NE) : (vc0 + ((size_t)b*NS + s)*NE);
                const float* qs = sh + b*NE;
                float4 k4[6], v4[6];
                #pragma unroll
                for (int c = 0; c < 6; c++){
                    int e = c*128 + lane*4;
                    if (iszero){ k4[c] = make_float4(0.f,0.f,0.f,0.f); v4[c] = k4[c]; }
                    else { k4[c] = *(const float4*)(ksrc + e); v4[c] = *(const float4*)(vsrc + e); }
                }
                if (ko0){
                    #pragma unroll
                    for (int c = 0; c < 6; c++){
                        int e = c*128 + lane*4;
                        *(float4*)(ko0 + ((size_t)b*NS1 + s)*NE + e) = k4[c];
                        *(float4*)(vo0 + ((size_t)b*NS1 + s)*NE + e) = v4[c];
                    }
                }
                float part[6];
                #pragma unroll
                for (int c = 0; c < 6; c++){
                    int e = c*128 + lane*4;
                    part[c] = k4[c].x*qs[e] + k4[c].y*qs[e+1] + k4[c].z*qs[e+2] + k4[c].w*qs[e+3];
                }
                #pragma unroll
                for (int c = 0; c < 6; c++){
                    float p = part[c];
                    p += __shfl_xor_sync(0xffffffffu, p, 8);
                    p += __shfl_xor_sync(0xffffffffu, p, 4);
                    p += __shfl_xor_sync(0xffffffffu, p, 2);
                    p += __shfl_xor_sync(0xffffffffu, p, 1);
                    part[c] = p;
                }
                if ((lane & 15) == 0){
                    int hb = lane >> 4;
                    bool msk = (mask[b*NS1 + s] == 0);
                    float abv = abl[s];
                    #pragma unroll
                    for (int c = 0; c < 6; c++)
                        g_scores[((size_t)b*NH + 2*c + hb)*NS1 + s] = msk ? -1e9f : (part[c]*0.125f + abv);
                }
            }
        }
        gsync();

        // ---- attn_sv: redundant softmax + weighted V --------------------------
        {
            float* sm   = sh;           // [1024]
            float* red  = sh + 1024;    // [24]
            float* cacc = sh + 1056;    // [512]
            for (int t = bid; t < NB*NH*2; t += GRID){
                int b = t / (NH*2), rem = t - b*(NH*2);
                int h = rem >> 1, ck = rem & 1;
                __syncthreads();
                const float* sr = g_scores + ((size_t)b*NH + h)*NS1;
                float a0 = sr[tid];
                float a1 = (tid < 256) ? sr[768 + tid] : -1e30f;
                float m = fmaxf(a0, a1);
                #pragma unroll
                for (int o = 16; o; o >>= 1) m = fmaxf(m, __shfl_xor_sync(0xffffffffu, m, o));
                if (lane == 0) red[warp] = m;
                __syncthreads();
                m = red[0];
                #pragma unroll
                for (int w2 = 1; w2 < 24; w2++) m = fmaxf(m, red[w2]);
                float e0v = expf(a0 - m);
                float e1v = (tid < 256) ? expf(a1 - m) : 0.f;
                float ssum = e0v + e1v;
                #pragma unroll
                for (int o = 16; o; o >>= 1) ssum += __shfl_xor_sync(0xffffffffu, ssum, o);
                __syncthreads();
                if (lane == 0) red[warp] = ssum;
                __syncthreads();
                float tot = red[0];
                #pragma unroll
                for (int w2 = 1; w2 < 24; w2++) tot += red[w2];
                float inv = 1.0f/tot;
                sm[tid] = e0v*inv;
                if (tid < 256) sm[768 + tid] = e1v*inv;
                __syncthreads();
                float acc = 0.f;
                int col = tid & 63, rp = (tid >> 6) & 7;
                if (tid < 512){
                    if (nkv){
                        const float* vo = nkv + (size_t)(l*2+1)*NB*(size_t)NS1*NE
                                        + (size_t)b*NS1*NE + h*ND + col;
                        #pragma unroll 8
                        for (int i = 0; i < 64; i++){
                            int s = ck*512 + i*8 + rp;
                            acc = fmaf(sm[s], vo[(size_t)s*NE], acc);
                        }
                    } else {
                        int lp = g_lp[b];
                        const float* vc = kv + (size_t)(l*2+1)*NB*(size_t)NS*NE + (size_t)b*NS*NE;
                        for (int i = 0; i < 64; i++){
                            int s = ck*512 + i*8 + rp;
                            float vv;
                            if (s == lp) vv = g_qkv[b*NE3 + 2*NE + h*ND + col];
                            else if (s == NS) vv = 0.f;
                            else vv = vc[(size_t)s*NE + h*ND + col];
                            acc = fmaf(sm[s], vv, acc);
                        }
                    }
                    cacc[tid] = acc;
                }
                __syncthreads();
                if (tid < 64){
                    float r = cacc[tid];
                    #pragma unroll
                    for (int p2 = 1; p2 < 8; p2++) r += cacc[tid + p2*64];
                    atomicAdd(&g_ctx[b*NE + h*ND + tid], r);
                }
            }
        }
        gsync();

        // ---- cproj: states += ctx @ cpw + cpb; zero qkv -----------------------
        for (int i = bid*TPB + tid; i < NB*NE3; i += GRID*TPB) g_qkv[i] = 0.f;
        for (int t = bid; t < 24; t += GRID){
            __syncthreads();
            if (tid < 256){
                int b2 = tid >> 5, e = tid & 31;
                sh[tid] = g_ctx[b2*NE + t*32 + e];
            }
            __syncthreads();
            int e0g = eg*8;
            int j = jt*4;
            float4 acc[8];
            #pragma unroll
            for (int b2 = 0; b2 < 8; b2++) acc[b2] = make_float4(0.f,0.f,0.f,0.f);
            const float* Wp = cpwl + (size_t)(t*32 + e0g)*NE + j;
            #pragma unroll
            for (int e = 0; e < 8; e++){
                float4 w4 = *(const float4*)(Wp + (size_t)e*NE);
                #pragma unroll
                for (int b2 = 0; b2 < 8; b2++){
                    float xv = sh[b2*32 + e0g + e];
                    acc[b2].x = fmaf(xv,w4.x,acc[b2].x); acc[b2].y = fmaf(xv,w4.y,acc[b2].y);
                    acc[b2].z = fmaf(xv,w4.z,acc[b2].z); acc[b2].w = fmaf(xv,w4.w,acc[b2].w);
                }
            }
            if (t == 0 && eg == 0){
                float4 bv = *(const float4*)(cpb + (size_t)l*NE + j);
                #pragma unroll
                for (int b2 = 0; b2 < 8; b2++){
                    acc[b2].x += bv.x; acc[b2].y += bv.y; acc[b2].z += bv.z; acc[b2].w += bv.w;
                }
            }
            #pragma unroll
            for (int b2 = 0; b2 < 8; b2++){
                float* p = g_states + (size_t)b2*NE + j;
                atomicAdd(p+0,acc[b2].x); atomicAdd(p+1,acc[b2].y);
                atomicAdd(p+2,acc[b2].z); atomicAdd(p+3,acc[b2].w);
            }
        }
        gsync();

        // ---- fc: ln2 (redundant) + fc GEMV; zero ctx --------------------------
        block_ln(ln2w + l*NE, ln2b + l*NE, sh);
        for (int i = bid*TPB + tid; i < NB*NE; i += GRID*TPB) g_ctx[i] = 0.f;
        __syncthreads();
        for (int t = bid; t < 96; t += GRID){
            int eb = t % 24, jb = t / 24;
            int e0 = eb*32 + eg*8;
            int j = jb*768 + jt*4;
            float4 acc[8];
            #pragma unroll
            for (int b2 = 0; b2 < 8; b2++) acc[b2] = make_float4(0.f,0.f,0.f,0.f);
            const float* Wp = fcwl + (size_t)e0*NFF + j;
            #pragma unroll
            for (int e = 0; e < 8; e++){
                float4 w4 = *(const float4*)(Wp + (size_t)e*NFF);
                #pragma unroll
                for (int b2 = 0; b2 < 8; b2++){
                    float xv = sh[b2*NE + e0 + e];
                    acc[b2].x = fmaf(xv,w4.x,acc[b2].x); acc[b2].y = fmaf(xv,w4.y,acc[b2].y);
                    acc[b2].z = fmaf(xv,w4.z,acc[b2].z); acc[b2].w = fmaf(xv,w4.w,acc[b2].w);
                }
            }
            if (e0 == 0){
                float4 bv = *(const float4*)(fcb + (size_t)l*NFF + j);
                #pragma unroll
                for (int b2 = 0; b2 < 8; b2++){
                    acc[b2].x += bv.x; acc[b2].y += bv.y; acc[b2].z += bv.z; acc[b2].w += bv.w;
                }
            }
            #pragma unroll
            for (int b2 = 0; b2 < 8; b2++){
                float* p = g_hbuf + (size_t)b2*NFF + j;
                atomicAdd(p+0,acc[b2].x); atomicAdd(p+1,acc[b2].y);
                atomicAdd(p+2,acc[b2].z); atomicAdd(p+3,acc[b2].w);
            }
        }
        gsync();

        // ---- proj: states += gelu(hbuf) @ prw + prb ---------------------------
        for (int t = bid; t < 96; t += GRID){
            __syncthreads();
            if (tid < 256){
                int b2 = tid >> 5, e = tid & 31;
                float v = g_hbuf[b2*NFF + t*32 + e];
                sh[tid] = 0.5f*v*(1.0f + erff(v*0.70710678118654752f));
            }
            __syncthreads();
            int e0g = eg*8;
            int j = jt*4;
            float4 acc[8];
            #pragma unroll
            for (int b2 = 0; b2 < 8; b2++) acc[b2] = make_float4(0.f,0.f,0.f,0.f);
            const float* Wp = prwl + (size_t)(t*32 + e0g)*NE + j;
            #pragma unroll
            for (int e = 0; e < 8; e++){
                float4 w4 = *(const float4*)(Wp + (size_t)e*NE);
                #pragma unroll
                for (int b2 = 0; b2 < 8; b2++){
                    float xv = sh[b2*32 + e0g + e];
                    acc[b2].x = fmaf(xv,w4.x,acc[b2].x); acc[b2].y = fmaf(xv,w4.y,acc[b2].y);
                    acc[b2].z = fmaf(xv,w4.z,acc[b2].z); acc[b2].w = fmaf(xv,w4.w,acc[b2].w);
                }
            }
            if (t == 0 && eg == 0){
                float4 bv = *(const float4*)(prb + (size_t)l*NE + j);
                #pragma unroll
                for (int b2 = 0; b2 < 8; b2++){
                    acc[b2].x += bv.x; acc[b2].y += bv.y; acc[b2].z += bv.z; acc[b2].w += bv.w;
                }
            }
            #pragma unroll
            for (int b2 = 0; b2 < 8; b2++){
                float* p = g_states + (size_t)b2*NE + j;
                atomicAdd(p+0,acc[b2].x); atomicAdd(p+1,acc[b2].y);
                atomicAdd(p+2,acc[b2].z); atomicAdd(p+3,acc[b2].w);
            }
        }
        gsync();
    }

    // ---------- lm head --------------------------------------------------------
    block_ln(lnfw, lnfb, sh);
    if (bid == 0 && tid < NB){ g_vmax[tid] = 0ull; g_vsum[tid] = 0.f; }
    __syncthreads();
    for (int t = bid*24 + warp; t < (NV+1)/2; t += GRID*24){
        long long t0 = (long long)t*2;
        bool has1 = (t0 + 1 < NV);
        const float* r0 = wte + (size_t)t0*NE;
        const float* r1 = has1 ? wte + (size_t)(t0+1)*NE : r0;
        float acc[16];
        #pragma unroll
        for (int i = 0; i < 16; i++) acc[i] = 0.f;
        #pragma unroll
        for (int c = 0; c < 6; c++){
            int e = c*128 + lane*4;
            float4 w0 = *(const float4*)(r0 + e);
            float4 w1 = *(const float4*)(r1 + e);
            #pragma unroll
            for (int b2 = 0; b2 < 8; b2++){
                float4 x4 = *(const float4*)&sh[b2*NE + e];
                acc[b2]   = fmaf(w0.x,x4.x, fmaf(w0.y,x4.y, fmaf(w0.z,x4.z, fmaf(w0.w,x4.w, acc[b2]))));
                acc[8+b2] = fmaf(w1.x,x4.x, fmaf(w1.y,x4.y, fmaf(w1.z,x4.z, fmaf(w1.w,x4.w, acc[8+b2]))));
            }
        }
        #pragma unroll
        for (int i = 0; i < 16; i++){
            float p = acc[i];
            p += __shfl_xor_sync(0xffffffffu, p, 16);
            p += __shfl_xor_sync(0xffffffffu, p, 8);
            p += __shfl_xor_sync(0xffffffffu, p, 4);
            p += __shfl_xor_sync(0xffffffffu, p, 2);
            p += __shfl_xor_sync(0xffffffffu, p, 1);
            acc[i] = p;
        }
        if (lane < 8){
            g_logits[(size_t)lane*NV + t0] = acc[lane];
            if (has1) g_logits[(size_t)lane*NV + t0 + 1] = acc[8 + lane];
        }
    }
    gsync();

    // ---------- finish A: per-batch max/argmax ---------------------------------
    {
        unsigned long long* shu = (unsigned long long*)sh;
        for (int b = 0; b < NB; b++){
            const float* lg = g_logits + (size_t)b*NV;
            float bm = -1e30f; int bi = 0;
            for (int t = bid*TPB + tid; t < NV; t += GRID*TPB){
                float v = lg[t];
                if (v > bm){ bm = v; bi = t; }
            }
            unsigned long long key = ((unsigned long long)ordf(bm) << 32)
                                   | (unsigned long long)(0x7fffffffu - (unsigned)bi);
            #pragma unroll
            for (int o = 16; o; o >>= 1){
                unsigned long long ok = __shfl_xor_sync(0xffffffffu, key, o);
                if (ok > key) key = ok;
            }
            if (lane == 0) shu[warp] = key;
            __syncthreads();
            if (tid == 0){
                unsigned long long k = shu[0];
                #pragma unroll
                for (int w2 = 1; w2 < 24; w2++) if (shu[w2] > k) k = shu[w2];
                atomicMax(&g_vmax[b], k);
            }
            __syncthreads();
        }
    }
    gsync();

    // ---------- finish B: exp-sum (+ write unnormalized probs) -----------------
    for (int b = 0; b < NB; b++){
        float mx = unordf((unsigned)(g_vmax[b] >> 32));
        const float* lg = g_logits + (size_t)b*NV;
        float s = 0.f;
        for (int t = bid*TPB + tid; t < NV; t += GRID*TPB){
            float ev = expf(lg[t] - mx);
            s += ev;
            if (probs) probs[(size_t)b*NV + t] = ev;
        }
        #pragma unroll
        for (int o = 16; o; o >>= 1) s += __shfl_xor_sync(0xffffffffu, s, o);
        if (lane == 0) sh[warp] = s;
        __syncthreads();
        if (tid == 0){
            float tot = sh[0];
            #pragma unroll
            for (int w2 = 1; w2 < 24; w2++) tot += sh[w2];
            atomicAdd(&g_vsum[b], tot);
        }
        __syncthreads();
    }
    gsync();

    // ---------- finish C: normalize + chosen -----------------------------------
    if (probs){
        for (int b = 0; b < NB; b++){
            float inv = 1.0f/g_vsum[b];
            for (int t = bid*TPB + tid; t < NV; t += GRID*TPB)
                probs[(size_t)b*NV + t] *= inv;
        }
    }
    if (bid == 0 && tid < NB){
        int am = (int)(0x7fffffffu - (unsigned)(g_vmax[tid] & 0xffffffffu));
        if (chosen_f) chosen_f[tid] = (float)am;
        if (chosen_i) chosen_i[tid] = am;
    }
}

// ---------------- launch --------------------------------------------------------
extern "C" void kernel_launch(void* const* d_in, const int* in_sizes, int n_in,
                              void* d_out, int out_size){
    const int*   ids  = (const int*)  d_in[0];
    const int*   mask = (const int*)  d_in[1];
    const float* kv   = (const float*)d_in[2];
    const float* wte  = (const float*)d_in[3];
    const float* wpe  = (const float*)d_in[4];
    const float* ln1w = (const float*)d_in[5];
    const float* ln1b = (const float*)d_in[6];
    const float* caw  = (const float*)d_in[7];
    const float* cab  = (const float*)d_in[8];
    const float* ab   = (const float*)d_in[9];
    const float* cpw  = (const float*)d_in[10];
    const float* cpb  = (const float*)d_in[11];
    const float* ln2w = (const float*)d_in[12];
    const float* ln2b = (const float*)d_in[13];
    const float* fcw  = (const float*)d_in[14];
    const float* fcb  = (const float*)d_in[15];
    const float* prw  = (const float*)d_in[16];
    const float* prb  = (const float*)d_in[17];
    const float* lnfw = (const float*)d_in[18];
    const float* lnfb = (const float*)d_in[19];

    long long nkvN  = (long long)NL*2*NB*NS1*NE;
    long long fullN = (long long)NB + (long long)NB*NV + nkvN;
    float* outf = (float*)d_out;
    float* chosen_f = nullptr; int* chosen_i = nullptr;
    float* probs = nullptr; float* nkv = nullptr;
    long long osz = (long long)out_size;
    if (osz == fullN){ chosen_f = outf; probs = outf + NB; nkv = outf + NB + (long long)NB*NV; }
    else if (osz == nkvN){ nkv = outf; }
    else if (osz == (long long)NB*NV){ probs = outf; }
    else if (osz == (long long)NB){ chosen_i = (int*)d_out; }
    else if (osz == (long long)NB + (long long)NB*NV){ chosen_f = outf; probs = outf + NB; }
    else {
        chosen_f = outf;
        if (osz >= (long long)NB + (long long)NB*NV) probs = outf + NB;
        if (osz >= fullN) nkv = outf + NB + (long long)NB*NV;
    }

    mega_kernel<<<GRID, TPB>>>(ids, mask, kv, wte, wpe, ln1w, ln1b, caw, cab, ab,
                               cpw, cpb, ln2w, ln2b, fcw, fcb, prw, prb, lnfw, lnfb,
                               nkv, probs, chosen_f, chosen_i);
}

// round 9
// speedup vs baseline: 1.5376x; 1.5096x over previous
#include <cuda_runtime.h>
#include <math.h>

#define NB 8
#define NL 12
#define NS 1023
#define NS1 1024
#define NE 768
#define NH 12
#define ND 64
#define NV 50257
#define NFF 3072
#define NE3 2304

// PDL: let dependents launch immediately, and wait for upstream writes.
#define PDL_PROLOG  do { \
    asm volatile("griddepcontrol.launch_dependents;"); \
    asm volatile("griddepcontrol.wait;"); \
} while(0)

// ---------------- scratch (device globals: no allocation allowed) -------------
__device__ __align__(16) float g_states[NB*NE];
__device__ __align__(16) float g_xln[NB*NE];
__device__ __align__(16) float g_qkv[NB*NE3];
__device__ __align__(16) float g_ctx[NB*NE];
__device__ __align__(16) float g_hbuf[NB*NFF];
__device__ __align__(16) float g_scores[NB*NH*NS1];
__device__ __align__(16) float g_logits[NB*NV];
__device__ int g_lp[NB];

// ---------------- embedding + last-position -----------------------------------
__global__ void embed_kernel(const int* __restrict__ ids, const int* __restrict__ mask,
                             const float* __restrict__ wte, const float* __restrict__ wpe){
    PDL_PROLOG;
    int b = blockIdx.x, tid = threadIdx.x;
    __shared__ int s_lp;
    if (tid < 32){
        int best = -1;
        for (int s = tid; s < NS1; s += 32)
            if (mask[b*NS1 + s] != 0) best = (s > best) ? s : best;
        for (int o = 16; o; o >>= 1){
            int ot = __shfl_xor_sync(0xffffffffu, best, o);
            best = (ot > best) ? ot : best;
        }
        if (tid == 0){ s_lp = best; g_lp[b] = best; }
    }
    __syncthreads();
    int lp  = s_lp;
    int tok = ids[b*NS1 + lp];
    for (int e = tid; e < NE; e += blockDim.x)
        g_states[b*NE + e] = wte[(size_t)tok*NE + e] + wpe[(size_t)lp*NE + e];
}

// ---------------- layernorm + scratch zeroing ----------------------------------
__global__ void ln_prep_kernel(const float* __restrict__ src, const float* __restrict__ w,
                               const float* __restrict__ bb, float* __restrict__ out,
                               float* z1, int n1, float* z2, int n2){
    PDL_PROLOG;
    int b = blockIdx.x, tid = threadIdx.x;
    __shared__ float red[256];
    const float* x = src + b*NE;
    float s = 0.f;
    for (int i = tid; i < NE; i += 256) s += x[i];
    red[tid] = s; __syncthreads();
    for (int o = 128; o; o >>= 1){ if (tid < o) red[tid] += red[tid+o]; __syncthreads(); }
    float mean = red[0] * (1.0f/NE);
    __syncthreads();
    float v = 0.f;
    for (int i = tid; i < NE; i += 256){ float d = x[i]-mean; v += d*d; }
    red[tid] = v; __syncthreads();
    for (int o = 128; o; o >>= 1){ if (tid < o) red[tid] += red[tid+o]; __syncthreads(); }
    float rs = rsqrtf(red[0]*(1.0f/NE) + 1e-5f);
    for (int i = tid; i < NE; i += 256)
        out[b*NE + i] = (x[i]-mean)*rs*w[i] + bb[i];
    int g = b*256 + tid;
    if (z1) for (int i = g; i < n1; i += 2048) z1[i] = 0.f;
    if (z2) for (int i = g; i < n2; i += 2048) z2[i] = 0.f;
}

// ---------------- batched GEMV: out[b,j] (+)= sum_e x[b,e]*W[e,j] (+ bias) -----
__global__ void gemv_kernel(const float* __restrict__ x, const float* __restrict__ W,
                            const float* __restrict__ bias, float* __restrict__ out,
                            int M, int N, int CH, int dogelu){
    PDL_PROLOG;
    __shared__ __align__(16) float xs[8*32];
    int tid = threadIdx.x;
    int e0 = blockIdx.y * CH;
    int ec = M - e0; if (ec > CH) ec = CH;
    for (int i = tid; i < 8*ec; i += blockDim.x){
        int b2 = i / ec, e = i - b2*ec;
        float v = x[b2*M + e0 + e];
        if (dogelu) v = 0.5f*v*(1.0f + erff(v*0.70710678118654752f));
        xs[b2*32 + e] = v;
    }
    __syncthreads();
    int j = (blockIdx.x*blockDim.x + tid)*4;
    if (j >= N) return;
    float4 acc[8];
    #pragma unroll
    for (int b2 = 0; b2 < 8; b2++) acc[b2] = make_float4(0.f,0.f,0.f,0.f);
    const float* Wp = W + (size_t)e0*N + j;
    for (int e = 0; e < ec; e++){
        float4 w4 = *(const float4*)Wp; Wp += N;
        #pragma unroll
        for (int b2 = 0; b2 < 8; b2++){
            float xv = xs[b2*32 + e];
            acc[b2].x = fmaf(xv, w4.x, acc[b2].x);
            acc[b2].y = fmaf(xv, w4.y, acc[b2].y);
            acc[b2].z = fmaf(xv, w4.z, acc[b2].z);
            acc[b2].w = fmaf(xv, w4.w, acc[b2].w);
        }
    }
    if (blockIdx.y == 0){
        float4 bv = *(const float4*)(bias + j);
        #pragma unroll
        for (int b2 = 0; b2 < 8; b2++){
            acc[b2].x += bv.x; acc[b2].y += bv.y; acc[b2].z += bv.z; acc[b2].w += bv.w;
        }
    }
    #pragma unroll
    for (int b2 = 0; b2 < 8; b2++){
        float* p = out + (size_t)b2*N + j;
        atomicAdd(p+0, acc[b2].x); atomicAdd(p+1, acc[b2].y);
        atomicAdd(p+2, acc[b2].z); atomicAdd(p+3, acc[b2].w);
    }
}

// ---------------- attention scores + K copy into new_kv ------------------------
// grid (B, 128) x 256 thr: warp per seq row (8 rows per block).
__global__ void attn_score_kernel(const float* __restrict__ kv, const float* __restrict__ abias,
                                  const int* __restrict__ mask, float* __restrict__ nkv, int l){
    PDL_PROLOG;
    int b = blockIdx.x, sc = blockIdx.y;
    int tid = threadIdx.x, warp = tid >> 5, lane = tid & 31;
    __shared__ __align__(16) float qs[NE];
    for (int i = tid; i < NE; i += 256) qs[i] = g_qkv[b*NE3 + i];
    __syncthreads();
    int lp = g_lp[b];
    const float* kc = kv  + ((size_t)(l*2+0)*NB + b)*(size_t)NS *NE;
    float*       ko = nkv ? nkv + ((size_t)(l*2+0)*NB + b)*(size_t)NS1*NE : nullptr;
    int s = sc*8 + warp;
    const float* src = nullptr;
    if (s == lp)      src = g_qkv + b*NE3 + NE;            // new K row
    else if (s != NS) src = kc + (size_t)s*NE;             // cache row
    float4 v4[6];
    #pragma unroll
    for (int c = 0; c < 6; c++){
        int e = c*128 + lane*4;
        v4[c] = src ? *(const float4*)(src + e) : make_float4(0.f,0.f,0.f,0.f);
    }
    if (ko){
        #pragma unroll
        for (int c = 0; c < 6; c++)
            __stcs((float4*)(ko + (size_t)s*NE + c*128 + lane*4), v4[c]);
    }
    float part[6];
    #pragma unroll
    for (int c = 0; c < 6; c++){
        int e = c*128 + lane*4;
        part[c] = v4[c].x*qs[e] + v4[c].y*qs[e+1] + v4[c].z*qs[e+2] + v4[c].w*qs[e+3];
    }
    #pragma unroll
    for (int c = 0; c < 6; c++){
        float p = part[c];
        p += __shfl_xor_sync(0xffffffffu, p, 8);
        p += __shfl_xor_sync(0xffffffffu, p, 4);
        p += __shfl_xor_sync(0xffffffffu, p, 2);
        p += __shfl_xor_sync(0xffffffffu, p, 1);
        part[c] = p;
    }
    if ((lane & 15) == 0){
        int hb = lane >> 4;                 // 0 or 1
        bool msk = (mask[b*NS1 + s] == 0);
        float ab = abias[s];
        #pragma unroll
        for (int c = 0; c < 6; c++){
            int h = 2*c + hb;
            g_scores[(b*NH + h)*NS1 + s] = msk ? -1e9f : (part[c]*0.125f + ab);
        }
    }
}

// ---------------- softmax over seq per (b,h), in place -------------------------
__global__ void softmax_kernel(){
    PDL_PROLOG;
    int bh = blockIdx.x, tid = threadIdx.x;
    float* row = g_scores + (size_t)bh*NS1;
    __shared__ float red[256];
    float v[4]; float m = -1e30f;
    #pragma unroll
    for (int k = 0; k < 4; k++){ v[k] = row[tid + k*256]; m = fmaxf(m, v[k]); }
    red[tid] = m; __syncthreads();
    for (int o = 128; o; o >>= 1){ if (tid < o) red[tid] = fmaxf(red[tid], red[tid+o]); __syncthreads(); }
    m = red[0]; __syncthreads();
    float s = 0.f;
    #pragma unroll
    for (int k = 0; k < 4; k++){ v[k] = expf(v[k]-m); s += v[k]; }
    red[tid] = s; __syncthreads();
    for (int o = 128; o; o >>= 1){ if (tid < o) red[tid] += red[tid+o]; __syncthreads(); }
    float inv = 1.0f/red[0];
    #pragma unroll
    for (int k = 0; k < 4; k++) row[tid + k*256] = v[k]*inv;
}

// ---------------- weighted-V accumulation + V copy into new_kv -----------------
// grid (B, 64) x 192 thr: block handles 16 seq rows; thread owns 4 head-dims.
__global__ void attn_v_kernel(const float* __restrict__ kv, float* __restrict__ nkv, int l){
    PDL_PROLOG;
    int b = blockIdx.x, sc = blockIdx.y, tid = threadIdx.x;
    int e = tid*4, h = tid >> 4;
    __shared__ __align__(16) float ws[NH*16];
    {
        int hh = tid >> 4, si = tid & 15;
        ws[tid] = g_scores[(b*NH + hh)*NS1 + sc*16 + si];
    }
    __syncthreads();
    int lp = g_lp[b];
    const float* vc = kv  + ((size_t)(l*2+1)*NB + b)*(size_t)NS *NE;
    float*       vo = nkv ? nkv + ((size_t)(l*2+1)*NB + b)*(size_t)NS1*NE : nullptr;
    float4 acc = make_float4(0.f,0.f,0.f,0.f);
    #pragma unroll 4
    for (int i = 0; i < 16; i++){
        int s = sc*16 + i;
        float w = ws[h*16 + i];
        float4 v4;
        if (s == lp)      v4 = *(const float4*)(g_qkv + b*NE3 + 2*NE + e);
        else if (s == NS) v4 = make_float4(0.f,0.f,0.f,0.f);
        else              v4 = *(const float4*)(vc + (size_t)s*NE + e);
        if (vo) __stcs((float4*)(vo + (size_t)s*NE + e), v4);
        acc.x = fmaf(w, v4.x, acc.x); acc.y = fmaf(w, v4.y, acc.y);
        acc.z = fmaf(w, v4.z, acc.z); acc.w = fmaf(w, v4.w, acc.w);
    }
    float* p = g_ctx + b*NE + e;
    atomicAdd(p+0, acc.x); atomicAdd(p+1, acc.y);
    atomicAdd(p+2, acc.z); atomicAdd(p+3, acc.w);
}

// ---------------- lm head: warp per 2 vocab rows, coalesced --------------------
__global__ void lm_kernel(const float* __restrict__ wte){
    PDL_PROLOG;
    __shared__ __align__(16) float xs[NB*NE];
    int tid = threadIdx.x;
    for (int i = tid; i < NB*NE; i += 256) xs[i] = g_xln[i];
    __syncthreads();
    int warp = tid >> 5, lane = tid & 31;
    long long t0 = (long long)blockIdx.x*16 + warp*2;
    if (t0 >= NV) return;
    bool has1 = (t0 + 1 < NV);
    const float* r0 = wte + (size_t)t0*NE;
    const float* r1 = has1 ? wte + (size_t)(t0+1)*NE : r0;
    float acc[16];
    #pragma unroll
    for (int i = 0; i < 16; i++) acc[i] = 0.f;
    #pragma unroll
    for (int c = 0; c < 6; c++){
        int e = c*128 + lane*4;
        float4 w0 = *(const float4*)(r0 + e);
        float4 w1 = *(const float4*)(r1 + e);
        #pragma unroll
        for (int b2 = 0; b2 < 8; b2++){
            float4 x4 = *(const float4*)&xs[b2*NE + e];
            acc[b2]   = fmaf(w0.x,x4.x, fmaf(w0.y,x4.y, fmaf(w0.z,x4.z, fmaf(w0.w,x4.w, acc[b2]))));
            acc[8+b2] = fmaf(w1.x,x4.x, fmaf(w1.y,x4.y, fmaf(w1.z,x4.z, fmaf(w1.w,x4.w, acc[8+b2]))));
        }
    }
    #pragma unroll
    for (int i = 0; i < 16; i++){
        float p = acc[i];
        p += __shfl_xor_sync(0xffffffffu, p, 16);
        p += __shfl_xor_sync(0xffffffffu, p, 8);
        p += __shfl_xor_sync(0xffffffffu, p, 4);
        p += __shfl_xor_sync(0xffffffffu, p, 2);
        p += __shfl_xor_sync(0xffffffffu, p, 1);
        acc[i] = p;
    }
    if (lane < 8){
        g_logits[(size_t)lane*NV + t0] = acc[lane];
        if (has1) g_logits[(size_t)lane*NV + t0 + 1] = acc[8 + lane];
    }
}

// ---------------- vocab softmax + argmax ---------------------------------------
__global__ void finish_kernel(float* __restrict__ probs, float* __restrict__ chosen_f,
                              int* __restrict__ chosen_i){
    PDL_PROLOG;
    int b = blockIdx.x, tid = threadIdx.x;
    __shared__ float rv[1024];
    __shared__ int   ri[1024];
    const float* lg = g_logits + (size_t)b*NV;
    float m = -1e30f; int mi = 0;
    for (int t = tid; t < NV; t += 1024){
        float v = lg[t];
        if (v > m){ m = v; mi = t; }
    }
    rv[tid] = m; ri[tid] = mi; __syncthreads();
    for (int o = 512; o; o >>= 1){
        if (tid < o){
            if (rv[tid+o] > rv[tid] || (rv[tid+o] == rv[tid] && ri[tid+o] < ri[tid])){
                rv[tid] = rv[tid+o]; ri[tid] = ri[tid+o];
            }
        }
        __syncthreads();
    }
    float mx = rv[0]; int am = ri[0]; __syncthreads();
    float s = 0.f;
    for (int t = tid; t < NV; t += 1024){
        float ev = expf(lg[t]-mx);
        s += ev;
        if (probs) probs[(size_t)b*NV + t] = ev;
    }
    rv[tid] = s; __syncthreads();
    for (int o = 512; o; o >>= 1){ if (tid < o) rv[tid] += rv[tid+o]; __syncthreads(); }
    float inv = 1.0f/rv[0];
    if (probs)
        for (int t = tid; t < NV; t += 1024)
            probs[(size_t)b*NV + t] *= inv;
    if (tid == 0){
        if (chosen_f) chosen_f[b] = (float)am;
        if (chosen_i) chosen_i[b] = am;
    }
}

// ---------------- PDL launch helper ---------------------------------------------
template <typename... ExpTypes, typename... ActTypes>
static inline void pdl_launch(void (*kern)(ExpTypes...), dim3 grid, dim3 block,
                              ActTypes... args){
    cudaLaunchConfig_t cfg = {};
    cfg.gridDim = grid;
    cfg.blockDim = block;
    cfg.dynamicSmemBytes = 0;
    cfg.stream = 0;
    cudaLaunchAttribute at[1];
    at[0].id = cudaLaunchAttributeProgrammaticStreamSerialization;
    at[0].val.programmaticStreamSerializationAllowed = 1;
    cfg.attrs = at;
    cfg.numAttrs = 1;
    cudaLaunchKernelEx(&cfg, kern, (ExpTypes)args...);
}

// ---------------- launch --------------------------------------------------------
extern "C" void kernel_launch(void* const* d_in, const int* in_sizes, int n_in,
                              void* d_out, int out_size){
    const int*   ids  = (const int*)  d_in[0];
    const int*   mask = (const int*)  d_in[1];
    const float* kv   = (const float*)d_in[2];
    const float* wte  = (const float*)d_in[3];
    const float* wpe  = (const float*)d_in[4];
    const float* ln1w = (const float*)d_in[5];
    const float* ln1b = (const float*)d_in[6];
    const float* caw  = (const float*)d_in[7];
    const float* cab  = (const float*)d_in[8];
    const float* ab   = (const float*)d_in[9];
    const float* cpw  = (const float*)d_in[10];
    const float* cpb  = (const float*)d_in[11];
    const float* ln2w = (const float*)d_in[12];
    const float* ln2b = (const float*)d_in[13];
    const float* fcw  = (const float*)d_in[14];
    const float* fcb  = (const float*)d_in[15];
    const float* prw  = (const float*)d_in[16];
    const float* prb  = (const float*)d_in[17];
    const float* lnfw = (const float*)d_in[18];
    const float* lnfb = (const float*)d_in[19];

    float *st, *xln, *qkvp, *ctxp, *hb;
    cudaGetSymbolAddress((void**)&st,   g_states);
    cudaGetSymbolAddress((void**)&xln,  g_xln);
    cudaGetSymbolAddress((void**)&qkvp, g_qkv);
    cudaGetSymbolAddress((void**)&ctxp, g_ctx);
    cudaGetSymbolAddress((void**)&hb,   g_hbuf);

    long long nkvN  = (long long)NL*2*NB*NS1*NE;                  // 150,994,944
    long long fullN = (long long)NB + (long long)NB*NV + nkvN;    // 151,397,008
    float* outf = (float*)d_out;
    float* chosen_f = nullptr; int* chosen_i = nullptr;
    float* probs = nullptr; float* nkv = nullptr;
    long long osz = (long long)out_size;
    if (osz == fullN){ chosen_f = outf; probs = outf + NB; nkv = outf + NB + (long long)NB*NV; }
    else if (osz == nkvN){ nkv = outf; }
    else if (osz == (long long)NB*NV){ probs = outf; }
    else if (osz == (long long)NB){ chosen_i = (int*)d_out; }
    else if (osz == (long long)NB + (long long)NB*NV){ chosen_f = outf; probs = outf + NB; }
    else {
        chosen_f = outf;
        if (osz >= (long long)NB + (long long)NB*NV) probs = outf + NB;
        if (osz >= fullN) nkv = outf + NB + (long long)NB*NV;
    }

    pdl_launch(embed_kernel, dim3(NB), dim3(256), ids, mask, wte, wpe);
    for (int l = 0; l < NL; l++){
        pdl_launch(ln_prep_kernel, dim3(NB), dim3(256),
                   (const float*)st, ln1w + l*NE, ln1b + l*NE, xln,
                   qkvp, NB*NE3, ctxp, NB*NE);
        pdl_launch(gemv_kernel, dim3(3,48), dim3(256),
                   (const float*)xln, caw + (size_t)l*NE*NE3, cab + (size_t)l*NE3,
                   qkvp, NE, NE3, 16, 0);
        pdl_launch(attn_score_kernel, dim3(NB,128), dim3(256),
                   kv, ab + (size_t)l*NS1, mask, nkv, l);
        pdl_launch(softmax_kernel, dim3(NB*NH), dim3(256));
        pdl_launch(attn_v_kernel, dim3(NB,64), dim3(192), kv, nkv, l);
        pdl_launch(gemv_kernel, dim3(1,48), dim3(256),
                   (const float*)ctxp, cpw + (size_t)l*NE*NE, cpb + (size_t)l*NE,
                   st, NE, NE, 16, 0);
        pdl_launch(ln_prep_kernel, dim3(NB), dim3(256),
                   (const float*)st, ln2w + l*NE, ln2b + l*NE, xln,
                   hb, NB*NFF, (float*)nullptr, 0);
        pdl_launch(gemv_kernel, dim3(3,48), dim3(256),
                   (const float*)xln, fcw + (size_t)l*NE*NFF, fcb + (size_t)l*NFF,
                   hb, NE, NFF, 16, 0);
        pdl_launch(gemv_kernel, dim3(1,128), dim3(256),
                   (const float*)hb, prw + (size_t)l*NFF*NE, prb + (size_t)l*NE,
                   st, NFF, NE, 24, 1);
    }
    pdl_launch(ln_prep_kernel, dim3(NB), dim3(256),
               (const float*)st, lnfw, lnfb, xln,
               (float*)nullptr, 0, (float*)nullptr, 0);
    pdl_launch(lm_kernel, dim3((NV + 15)/16), dim3(256), wte);
    pdl_launch(finish_kernel, dim3(NB), dim3(1024), probs, chosen_f, chosen_i);
}

// round 10
// speedup vs baseline: 1.6502x; 1.0732x over previous
#include <cuda_runtime.h>
#include <math.h>

#define NB 8
#define NL 12
#define NS 1023
#define NS1 1024
#define NE 768
#define NH 12
#define ND 64
#define NV 50257
#define NFF 3072
#define NE3 2304

#define PDL_PROLOG  do { \
    asm volatile("griddepcontrol.launch_dependents;"); \
    asm volatile("griddepcontrol.wait;"); \
} while(0)

// ---------------- scratch (device globals) -------------------------------------
__device__ __align__(16) float g_states[NB*NE];
__device__ __align__(16) float g_xln[NB*NE];
__device__ __align__(16) float g_qkv[NB*NE3];
__device__ __align__(16) float g_ctx[NB*NE];
__device__ __align__(16) float g_hbuf[NB*NFF];
__device__ __align__(16) float g_scores[NB*NH*NS1];
__device__ __align__(16) float g_logits[NB*NV];
__device__ int g_lp[NB];

// ---------------- embedding + last-position; zero qkv & ctx --------------------
__global__ void embed_kernel(const int* __restrict__ ids, const int* __restrict__ mask,
                             const float* __restrict__ wte, const float* __restrict__ wpe){
    PDL_PROLOG;
    int b = blockIdx.x, tid = threadIdx.x;
    __shared__ int s_lp;
    if (tid < 32){
        int best = -1;
        for (int s = tid; s < NS1; s += 32)
            if (mask[b*NS1 + s] != 0) best = (s > best) ? s : best;
        for (int o = 16; o; o >>= 1){
            int ot = __shfl_xor_sync(0xffffffffu, best, o);
            best = (ot > best) ? ot : best;
        }
        if (tid == 0){ s_lp = best; g_lp[b] = best; }
    }
    __syncthreads();
    int lp  = s_lp;
    int tok = ids[b*NS1 + lp];
    for (int e = tid; e < NE; e += blockDim.x)
        g_states[b*NE + e] = wte[(size_t)tok*NE + e] + wpe[(size_t)lp*NE + e];
    int g = b*256 + tid;
    for (int i = g; i < NB*NE3; i += NB*256) g_qkv[i] = 0.f;
    for (int i = g; i < NB*NE;  i += NB*256) g_ctx[i] = 0.f;
}

// ---------------- final layernorm (single node before lm) ----------------------
__global__ void ln_prep_kernel(const float* __restrict__ w, const float* __restrict__ bb){
    PDL_PROLOG;
    int b = blockIdx.x, tid = threadIdx.x;
    __shared__ float red[256];
    const float* x = g_states + b*NE;
    float s = 0.f;
    for (int i = tid; i < NE; i += 256) s += x[i];
    red[tid] = s; __syncthreads();
    for (int o = 128; o; o >>= 1){ if (tid < o) red[tid] += red[tid+o]; __syncthreads(); }
    float mean = red[0] * (1.0f/NE);
    __syncthreads();
    float v = 0.f;
    for (int i = tid; i < NE; i += 256){ float d = x[i]-mean; v += d*d; }
    red[tid] = v; __syncthreads();
    for (int o = 128; o; o >>= 1){ if (tid < o) red[tid] += red[tid+o]; __syncthreads(); }
    float rs = rsqrtf(red[0]*(1.0f/NE) + 1e-5f);
    for (int i = tid; i < NE; i += 256)
        g_xln[b*NE + i] = (x[i]-mean)*rs*w[i] + bb[i];
}

// ---------------- GEMV with fused redundant layernorm of g_states --------------
// grid (jBlocks, M/CH) x 256. Each block: 8 warps do LN of the 8 batch rows,
// keep only the [e0,e0+CH) slice in smem, then unrolled GEMV with atomic out.
template<int CH>
__global__ void gemv_ln_kernel(const float* __restrict__ lnw, const float* __restrict__ lnb,
                               const float* __restrict__ W, const float* __restrict__ bias,
                               float* __restrict__ out, int N){
    PDL_PROLOG;
    __shared__ __align__(16) float xs[8*CH];
    int tid = threadIdx.x, warp = tid >> 5, lane = tid & 31;
    int e0 = blockIdx.y * CH;
    {   // LN of row `warp`
        const float* x = g_states + warp*NE;
        float s = 0.f;
        for (int i = lane; i < NE; i += 32) s += x[i];
        #pragma unroll
        for (int o = 16; o; o >>= 1) s += __shfl_xor_sync(0xffffffffu, s, o);
        float mean = s*(1.0f/NE);
        float v = 0.f;
        for (int i = lane; i < NE; i += 32){ float d = x[i]-mean; v += d*d; }
        #pragma unroll
        for (int o = 16; o; o >>= 1) v += __shfl_xor_sync(0xffffffffu, v, o);
        float rs = rsqrtf(v*(1.0f/NE) + 1e-5f);
        for (int i = lane; i < CH; i += 32){
            int e = e0 + i;
            xs[warp*CH + i] = (x[e]-mean)*rs*lnw[e] + lnb[e];
        }
    }
    __syncthreads();
    int j = (blockIdx.x*256 + tid)*4;
    if (j >= N) return;
    float4 acc[8];
    #pragma unroll
    for (int b2 = 0; b2 < 8; b2++) acc[b2] = make_float4(0.f,0.f,0.f,0.f);
    const float* Wp = W + (size_t)e0*N + j;
    #pragma unroll
    for (int e = 0; e < CH; e++){
        float4 w4 = *(const float4*)(Wp + (size_t)e*N);
        #pragma unroll
        for (int b2 = 0; b2 < 8; b2++){
            float xv = xs[b2*CH + e];
            acc[b2].x = fmaf(xv,w4.x,acc[b2].x); acc[b2].y = fmaf(xv,w4.y,acc[b2].y);
            acc[b2].z = fmaf(xv,w4.z,acc[b2].z); acc[b2].w = fmaf(xv,w4.w,acc[b2].w);
        }
    }
    if (blockIdx.y == 0){
        float4 bv = *(const float4*)(bias + j);
        #pragma unroll
        for (int b2 = 0; b2 < 8; b2++){
            acc[b2].x += bv.x; acc[b2].y += bv.y; acc[b2].z += bv.z; acc[b2].w += bv.w;
        }
    }
    #pragma unroll
    for (int b2 = 0; b2 < 8; b2++){
        float* p = out + (size_t)b2*N + j;
        atomicAdd(p+0,acc[b2].x); atomicAdd(p+1,acc[b2].y);
        atomicAdd(p+2,acc[b2].z); atomicAdd(p+3,acc[b2].w);
    }
}

// ---------------- plain GEMV (optional gelu) + optional buffer zeroing ---------
template<int CH, int DOGELU>
__global__ void gemv_kernel(const float* __restrict__ x, const float* __restrict__ W,
                            const float* __restrict__ bias, float* __restrict__ out,
                            int M, int N, float* zbuf, int zn){
    PDL_PROLOG;
    __shared__ __align__(16) float xs[8*CH];
    int tid = threadIdx.x;
    int e0 = blockIdx.y * CH;
    if (zbuf){
        int nb = gridDim.x*gridDim.y;
        for (int i = (blockIdx.y*gridDim.x + blockIdx.x)*256 + tid; i < zn; i += nb*256)
            zbuf[i] = 0.f;
    }
    for (int i = tid; i < 8*CH; i += 256){
        int b2 = i / CH, e = i - b2*CH;
        float v = x[b2*M + e0 + e];
        if (DOGELU) v = 0.5f*v*(1.0f + erff(v*0.70710678118654752f));
        xs[b2*CH + e] = v;
    }
    __syncthreads();
    int j = (blockIdx.x*256 + tid)*4;
    if (j >= N) return;
    float4 acc[8];
    #pragma unroll
    for (int b2 = 0; b2 < 8; b2++) acc[b2] = make_float4(0.f,0.f,0.f,0.f);
    const float* Wp = W + (size_t)e0*N + j;
    #pragma unroll
    for (int e = 0; e < CH; e++){
        float4 w4 = *(const float4*)(Wp + (size_t)e*N);
        #pragma unroll
        for (int b2 = 0; b2 < 8; b2++){
            float xv = xs[b2*CH + e];
            acc[b2].x = fmaf(xv,w4.x,acc[b2].x); acc[b2].y = fmaf(xv,w4.y,acc[b2].y);
            acc[b2].z = fmaf(xv,w4.z,acc[b2].z); acc[b2].w = fmaf(xv,w4.w,acc[b2].w);
        }
    }
    if (blockIdx.y == 0){
        float4 bv = *(const float4*)(bias + j);
        #pragma unroll
        for (int b2 = 0; b2 < 8; b2++){
            acc[b2].x += bv.x; acc[b2].y += bv.y; acc[b2].z += bv.z; acc[b2].w += bv.w;
        }
    }
    #pragma unroll
    for (int b2 = 0; b2 < 8; b2++){
        float* p = out + (size_t)b2*N + j;
        atomicAdd(p+0,acc[b2].x); atomicAdd(p+1,acc[b2].y);
        atomicAdd(p+2,acc[b2].z); atomicAdd(p+3,acc[b2].w);
    }
}

// ---------------- K+V copy into new_kv + attention scores; zero hbuf -----------
// grid (B, 128) x 256: warp per seq row; 12 in-flight float4 loads per warp.
__global__ void attn_kv_kernel(const float* __restrict__ kv, const float* __restrict__ abias,
                               const int* __restrict__ mask, float* __restrict__ nkv, int l){
    PDL_PROLOG;
    int b = blockIdx.x, sc = blockIdx.y;
    int tid = threadIdx.x, warp = tid >> 5, lane = tid & 31;
    {   // zero hbuf for this layer's fc accumulation
        for (int i = (b*128 + sc)*256 + tid; i < NB*NFF; i += NB*128*256) g_hbuf[i] = 0.f;
    }
    __shared__ __align__(16) float qs[NE];
    for (int i = tid; i < NE; i += 256) qs[i] = g_qkv[b*NE3 + i];
    __syncthreads();
    int lp = g_lp[b];
    const float* kc = kv + ((size_t)(l*2+0)*NB + b)*(size_t)NS*NE;
    const float* vc = kv + ((size_t)(l*2+1)*NB + b)*(size_t)NS*NE;
    float* ko = nkv ? nkv + ((size_t)(l*2+0)*NB + b)*(size_t)NS1*NE : nullptr;
    float* vo = nkv ? nkv + ((size_t)(l*2+1)*NB + b)*(size_t)NS1*NE : nullptr;
    int s = sc*8 + warp;
    bool isnew = (s == lp);
    bool iszero = (s == NS) && !isnew;
    const float* ksrc = isnew ? (g_qkv + b*NE3 + NE)   : (kc + (size_t)s*NE);
    const float* vsrc = isnew ? (g_qkv + b*NE3 + 2*NE) : (vc + (size_t)s*NE);
    float4 k4[6], v4[6];
    #pragma unroll
    for (int c = 0; c < 6; c++){
        int e = c*128 + lane*4;
        if (iszero){ k4[c] = make_float4(0.f,0.f,0.f,0.f); v4[c] = k4[c]; }
        else { k4[c] = *(const float4*)(ksrc + e); v4[c] = *(const float4*)(vsrc + e); }
    }
    if (ko){
        #pragma unroll
        for (int c = 0; c < 6; c++){
            int e = c*128 + lane*4;
            __stcs((float4*)(ko + (size_t)s*NE + e), k4[c]);     // K never re-read
            *(float4*)(vo + (size_t)s*NE + e) = v4[c];           // V re-read by attn_sv (keep cached)
        }
    }
    float part[6];
    #pragma unroll
    for (int c = 0; c < 6; c++){
        int e = c*128 + lane*4;
        part[c] = k4[c].x*qs[e] + k4[c].y*qs[e+1] + k4[c].z*qs[e+2] + k4[c].w*qs[e+3];
    }
    #pragma unroll
    for (int c = 0; c < 6; c++){
        float p = part[c];
        p += __shfl_xor_sync(0xffffffffu, p, 8);
        p += __shfl_xor_sync(0xffffffffu, p, 4);
        p += __shfl_xor_sync(0xffffffffu, p, 2);
        p += __shfl_xor_sync(0xffffffffu, p, 1);
        part[c] = p;
    }
    if ((lane & 15) == 0){
        int hb = lane >> 4;
        bool msk = (mask[b*NS1 + s] == 0);
        float ab = abias[s];
        #pragma unroll
        for (int c = 0; c < 6; c++){
            int h = 2*c + hb;
            g_scores[(b*NH + h)*NS1 + s] = msk ? -1e9f : (part[c]*0.125f + ab);
        }
    }
}

// ---------------- softmax + weighted-V (V from L2-hot new_kv) ------------------
// grid (B, H, 8) x 128: block = one (b,h) x 128-row chunk; redundant softmax.
__global__ void attn_sv_kernel(const float* __restrict__ kv, const float* __restrict__ nkv, int l){
    PDL_PROLOG;
    int b = blockIdx.x, h = blockIdx.y, ck = blockIdx.z;
    int tid = threadIdx.x;
    __shared__ float sm[NS1];
    __shared__ float red[4];
    const float* sr = g_scores + ((size_t)b*NH + h)*NS1;
    float v[8]; float m = -1e30f;
    #pragma unroll
    for (int k = 0; k < 8; k++){ v[k] = sr[tid + k*128]; m = fmaxf(m, v[k]); }
    #pragma unroll
    for (int o = 16; o; o >>= 1) m = fmaxf(m, __shfl_xor_sync(0xffffffffu, m, o));
    if ((tid & 31) == 0) red[tid >> 5] = m;
    __syncthreads();
    m = fmaxf(fmaxf(red[0], red[1]), fmaxf(red[2], red[3]));
    float ssum = 0.f;
    #pragma unroll
    for (int k = 0; k < 8; k++){ v[k] = expf(v[k] - m); ssum += v[k]; }
    #pragma unroll
    for (int o = 16; o; o >>= 1) ssum += __shfl_xor_sync(0xffffffffu, ssum, o);
    __syncthreads();
    if ((tid & 31) == 0) red[tid >> 5] = ssum;
    __syncthreads();
    float inv = 1.0f/(red[0]+red[1]+red[2]+red[3]);
    #pragma unroll
    for (int k = 0; k < 8; k++) sm[tid + k*128] = v[k]*inv;
    __syncthreads();
    int col = tid & 63, rp = tid >> 6;
    float acc = 0.f;
    if (nkv){
        const float* vo = nkv + ((size_t)(l*2+1)*NB + b)*(size_t)NS1*NE + h*ND + col;
        #pragma unroll 8
        for (int i = 0; i < 64; i++){
            int s = ck*128 + 2*i + rp;
            acc = fmaf(sm[s], vo[(size_t)s*NE], acc);
        }
    } else {
        int lp = g_lp[b];
        const float* vc = kv + ((size_t)(l*2+1)*NB + b)*(size_t)NS*NE;
        for (int i = 0; i < 64; i++){
            int s = ck*128 + 2*i + rp;
            float vv;
            if (s == lp) vv = g_qkv[b*NE3 + 2*NE + h*ND + col];
            else if (s == NS) vv = 0.f;
            else vv = vc[(size_t)s*NE + h*ND + col];
            acc = fmaf(sm[s], vv, acc);
        }
    }
    __shared__ float cacc[128];
    cacc[tid] = acc; __syncthreads();
    if (tid < 64)
        atomicAdd(&g_ctx[b*NE + h*ND + tid], cacc[tid] + cacc[tid + 64]);
}

// ---------------- lm head: warp per 2 vocab rows, coalesced --------------------
__global__ void lm_kernel(const float* __restrict__ wte){
    PDL_PROLOG;
    __shared__ __align__(16) float xs[NB*NE];
    int tid = threadIdx.x;
    for (int i = tid; i < NB*NE; i += 256) xs[i] = g_xln[i];
    __syncthreads();
    int warp = tid >> 5, lane = tid & 31;
    long long t0 = (long long)blockIdx.x*16 + warp*2;
    if (t0 >= NV) return;
    bool has1 = (t0 + 1 < NV);
    const float* r0 = wte + (size_t)t0*NE;
    const float* r1 = has1 ? wte + (size_t)(t0+1)*NE : r0;
    float acc[16];
    #pragma unroll
    for (int i = 0; i < 16; i++) acc[i] = 0.f;
    #pragma unroll
    for (int c = 0; c < 6; c++){
        int e = c*128 + lane*4;
        float4 w0 = *(const float4*)(r0 + e);
        float4 w1 = *(const float4*)(r1 + e);
        #pragma unroll
        for (int b2 = 0; b2 < 8; b2++){
            float4 x4 = *(const float4*)&xs[b2*NE + e];
            acc[b2]   = fmaf(w0.x,x4.x, fmaf(w0.y,x4.y, fmaf(w0.z,x4.z, fmaf(w0.w,x4.w, acc[b2]))));
            acc[8+b2] = fmaf(w1.x,x4.x, fmaf(w1.y,x4.y, fmaf(w1.z,x4.z, fmaf(w1.w,x4.w, acc[8+b2]))));
        }
    }
    #pragma unroll
    for (int i = 0; i < 16; i++){
        float p = acc[i];
        p += __shfl_xor_sync(0xffffffffu, p, 16);
        p += __shfl_xor_sync(0xffffffffu, p, 8);
        p += __shfl_xor_sync(0xffffffffu, p, 4);
        p += __shfl_xor_sync(0xffffffffu, p, 2);
        p += __shfl_xor_sync(0xffffffffu, p, 1);
        acc[i] = p;
    }
    if (lane < 8){
        g_logits[(size_t)lane*NV + t0] = acc[lane];
        if (has1) g_logits[(size_t)lane*NV + t0 + 1] = acc[8 + lane];
    }
}

// ---------------- vocab softmax + argmax ---------------------------------------
__global__ void finish_kernel(float* __restrict__ probs, float* __restrict__ chosen_f,
                              int* __restrict__ chosen_i){
    PDL_PROLOG;
    int b = blockIdx.x, tid = threadIdx.x;
    __shared__ float rv[1024];
    __shared__ int   ri[1024];
    const float* lg = g_logits + (size_t)b*NV;
    float m = -1e30f; int mi = 0;
    for (int t = tid; t < NV; t += 1024){
        float v = lg[t];
        if (v > m){ m = v; mi = t; }
    }
    rv[tid] = m; ri[tid] = mi; __syncthreads();
    for (int o = 512; o; o >>= 1){
        if (tid < o){
            if (rv[tid+o] > rv[tid] || (rv[tid+o] == rv[tid] && ri[tid+o] < ri[tid])){
                rv[tid] = rv[tid+o]; ri[tid] = ri[tid+o];
            }
        }
        __syncthreads();
    }
    float mx = rv[0]; int am = ri[0]; __syncthreads();
    float s = 0.f;
    for (int t = tid; t < NV; t += 1024){
        float ev = expf(lg[t]-mx);
        s += ev;
        if (probs) probs[(size_t)b*NV + t] = ev;
    }
    rv[tid] = s; __syncthreads();
    for (int o = 512; o; o >>= 1){ if (tid < o) rv[tid] += rv[tid+o]; __syncthreads(); }
    float inv = 1.0f/rv[0];
    if (probs)
        for (int t = tid; t < NV; t += 1024)
            probs[(size_t)b*NV + t] *= inv;
    if (tid == 0){
        if (chosen_f) chosen_f[b] = (float)am;
        if (chosen_i) chosen_i[b] = am;
    }
}

// ---------------- PDL launch helper ---------------------------------------------
template <typename... ExpTypes, typename... ActTypes>
static inline void pdl_launch(void (*kern)(ExpTypes...), dim3 grid, dim3 block,
                              ActTypes... args){
    cudaLaunchConfig_t cfg = {};
    cfg.gridDim = grid;
    cfg.blockDim = block;
    cfg.dynamicSmemBytes = 0;
    cfg.stream = 0;
    cudaLaunchAttribute at[1];
    at[0].id = cudaLaunchAttributeProgrammaticStreamSerialization;
    at[0].val.programmaticStreamSerializationAllowed = 1;
    cfg.attrs = at;
    cfg.numAttrs = 1;
    cudaLaunchKernelEx(&cfg, kern, (ExpTypes)args...);
}

// ---------------- launch --------------------------------------------------------
extern "C" void kernel_launch(void* const* d_in, const int* in_sizes, int n_in,
                              void* d_out, int out_size){
    const int*   ids  = (const int*)  d_in[0];
    const int*   mask = (const int*)  d_in[1];
    const float* kv   = (const float*)d_in[2];
    const float* wte  = (const float*)d_in[3];
    const float* wpe  = (const float*)d_in[4];
    const float* ln1w = (const float*)d_in[5];
    const float* ln1b = (const float*)d_in[6];
    const float* caw  = (const float*)d_in[7];
    const float* cab  = (const float*)d_in[8];
    const float* ab   = (const float*)d_in[9];
    const float* cpw  = (const float*)d_in[10];
    const float* cpb  = (const float*)d_in[11];
    const float* ln2w = (const float*)d_in[12];
    const float* ln2b = (const float*)d_in[13];
    const float* fcw  = (const float*)d_in[14];
    const float* fcb  = (const float*)d_in[15];
    const float* prw  = (const float*)d_in[16];
    const float* prb  = (const float*)d_in[17];
    const float* lnfw = (const float*)d_in[18];
    const float* lnfb = (const float*)d_in[19];

    float *st, *qkvp, *ctxp, *hb;
    cudaGetSymbolAddress((void**)&st,   g_states);
    cudaGetSymbolAddress((void**)&qkvp, g_qkv);
    cudaGetSymbolAddress((void**)&ctxp, g_ctx);
    cudaGetSymbolAddress((void**)&hb,   g_hbuf);

    long long nkvN  = (long long)NL*2*NB*NS1*NE;                  // 150,994,944
    long long fullN = (long long)NB + (long long)NB*NV + nkvN;    // 151,397,008
    float* outf = (float*)d_out;
    float* chosen_f = nullptr; int* chosen_i = nullptr;
    float* probs = nullptr; float* nkv = nullptr;
    long long osz = (long long)out_size;
    if (osz == fullN){ chosen_f = outf; probs = outf + NB; nkv = outf + NB + (long long)NB*NV; }
    else if (osz == nkvN){ nkv = outf; }
    else if (osz == (long long)NB*NV){ probs = outf; }
    else if (osz == (long long)NB){ chosen_i = (int*)d_out; }
    else if (osz == (long long)NB + (long long)NB*NV){ chosen_f = outf; probs = outf + NB; }
    else {
        chosen_f = outf;
        if (osz >= (long long)NB + (long long)NB*NV) probs = outf + NB;
        if (osz >= fullN) nkv = outf + NB + (long long)NB*NV;
    }

    pdl_launch(embed_kernel, dim3(NB), dim3(256), ids, mask, wte, wpe);
    for (int l = 0; l < NL; l++){
        // 1) ln1 + qkv GEMV
        pdl_launch(gemv_ln_kernel<16>, dim3(3,48), dim3(256),
                   ln1w + l*NE, ln1b + l*NE,
                   caw + (size_t)l*NE*NE3, cab + (size_t)l*NE3, qkvp, NE3);
        // 2) K/V copy + scores (also zeroes hbuf)
        pdl_launch(attn_kv_kernel, dim3(NB,128), dim3(256),
                   kv, ab + (size_t)l*NS1, mask, nkv, l);
        // 3) softmax + weighted V
        pdl_launch(attn_sv_kernel, dim3(NB,NH,8), dim3(128), kv, (const float*)nkv, l);
        // 4) cproj (also zeroes qkv for next layer)
        pdl_launch(gemv_kernel<16,0>, dim3(1,48), dim3(256),
                   (const float*)ctxp, cpw + (size_t)l*NE*NE, cpb + (size_t)l*NE,
                   st, NE, NE, qkvp, NB*NE3);
        // 5) ln2 + fc GEMV
        pdl_launch(gemv_ln_kernel<16>, dim3(3,48), dim3(256),
                   ln2w + l*NE, ln2b + l*NE,
                   fcw + (size_t)l*NE*NFF, fcb + (size_t)l*NFF, hb, NFF);
        // 6) proj with gelu (also zeroes ctx for next layer)
        pdl_launch(gemv_kernel<24,1>, dim3(1,128), dim3(256),
                   (const float*)hb, prw + (size_t)l*NFF*NE, prb + (size_t)l*NE,
                   st, NFF, NE, ctxp, NB*NE);
    }
    pdl_launch(ln_prep_kernel, dim3(NB), dim3(256), lnfw, lnfb);
    pdl_launch(lm_kernel, dim3((NV + 15)/16), dim3(256), wte);
    pdl_launch(finish_kernel, dim3(NB), dim3(1024), probs, chosen_f, chosen_i);
}

// round 11
// speedup vs baseline: 1.8592x; 1.1267x over previous
#include <cuda_runtime.h>
#include <math.h>

#define NB 8
#define NL 12
#define NS 1023
#define NS1 1024
#define NE 768
#define NH 12
#define ND 64
#define NV 50257
#define NFF 3072
#define NE3 2304

#define PDL_PROLOG  do { \
    asm volatile("griddepcontrol.launch_dependents;"); \
    asm volatile("griddepcontrol.wait;"); \
} while(0)

// ---------------- scratch (device globals) -------------------------------------
__device__ __align__(16) float g_states[NB*NE];
__device__ __align__(16) float g_qkv[NB*NE3];
__device__ __align__(16) float g_ctx[NB*NE];
__device__ __align__(16) float g_hbuf[NB*NFF];
__device__ __align__(16) float g_scores[NB*NH*NS1];
__device__ __align__(16) float g_logits[NB*NV];
__device__ int g_lp[NB];

// ---------------- embedding + last-position; zero qkv & ctx --------------------
__global__ void embed_kernel(const int* __restrict__ ids, const int* __restrict__ mask,
                             const float* __restrict__ wte, const float* __restrict__ wpe){
    PDL_PROLOG;
    int b = blockIdx.x, tid = threadIdx.x;
    __shared__ int s_lp;
    if (tid < 32){
        int best = -1;
        for (int s = tid; s < NS1; s += 32)
            if (mask[b*NS1 + s] != 0) best = (s > best) ? s : best;
        for (int o = 16; o; o >>= 1){
            int ot = __shfl_xor_sync(0xffffffffu, best, o);
            best = (ot > best) ? ot : best;
        }
        if (tid == 0){ s_lp = best; g_lp[b] = best; }
    }
    __syncthreads();
    int lp  = s_lp;
    int tok = ids[b*NS1 + lp];
    for (int e = tid; e < NE; e += blockDim.x)
        g_states[b*NE + e] = wte[(size_t)tok*NE + e] + wpe[(size_t)lp*NE + e];
    int g = b*256 + tid;
    for (int i = g; i < NB*NE3; i += NB*256) g_qkv[i] = 0.f;
    for (int i = g; i < NB*NE;  i += NB*256) g_ctx[i] = 0.f;
}

// ---------------- GEMV with fused redundant layernorm of g_states --------------
template<int CH>
__global__ void gemv_ln_kernel(const float* __restrict__ lnw, const float* __restrict__ lnb,
                               const float* __restrict__ W, const float* __restrict__ bias,
                               float* __restrict__ out, int N){
    PDL_PROLOG;
    __shared__ __align__(16) float xs[8*CH];
    int tid = threadIdx.x, warp = tid >> 5, lane = tid & 31;
    int e0 = blockIdx.y * CH;
    {   // LN of row `warp`
        const float* x = g_states + warp*NE;
        float s = 0.f;
        for (int i = lane; i < NE; i += 32) s += x[i];
        #pragma unroll
        for (int o = 16; o; o >>= 1) s += __shfl_xor_sync(0xffffffffu, s, o);
        float mean = s*(1.0f/NE);
        float v = 0.f;
        for (int i = lane; i < NE; i += 32){ float d = x[i]-mean; v += d*d; }
        #pragma unroll
        for (int o = 16; o; o >>= 1) v += __shfl_xor_sync(0xffffffffu, v, o);
        float rs = rsqrtf(v*(1.0f/NE) + 1e-5f);
        for (int i = lane; i < CH; i += 32){
            int e = e0 + i;
            xs[warp*CH + i] = (x[e]-mean)*rs*lnw[e] + lnb[e];
        }
    }
    __syncthreads();
    int j = (blockIdx.x*256 + tid)*4;
    if (j >= N) return;
    float4 acc[8];
    #pragma unroll
    for (int b2 = 0; b2 < 8; b2++) acc[b2] = make_float4(0.f,0.f,0.f,0.f);
    const float* Wp = W + (size_t)e0*N + j;
    #pragma unroll
    for (int e = 0; e < CH; e++){
        float4 w4 = *(const float4*)(Wp + (size_t)e*N);
        #pragma unroll
        for (int b2 = 0; b2 < 8; b2++){
            float xv = xs[b2*CH + e];
            acc[b2].x = fmaf(xv,w4.x,acc[b2].x); acc[b2].y = fmaf(xv,w4.y,acc[b2].y);
            acc[b2].z = fmaf(xv,w4.z,acc[b2].z); acc[b2].w = fmaf(xv,w4.w,acc[b2].w);
        }
    }
    if (blockIdx.y == 0){
        float4 bv = *(const float4*)(bias + j);
        #pragma unroll
        for (int b2 = 0; b2 < 8; b2++){
            acc[b2].x += bv.x; acc[b2].y += bv.y; acc[b2].z += bv.z; acc[b2].w += bv.w;
        }
    }
    #pragma unroll
    for (int b2 = 0; b2 < 8; b2++){
        float* p = out + (size_t)b2*N + j;
        atomicAdd(p+0,acc[b2].x); atomicAdd(p+1,acc[b2].y);
        atomicAdd(p+2,acc[b2].z); atomicAdd(p+3,acc[b2].w);
    }
}

// ---------------- plain GEMV (optional gelu) + optional buffer zeroing ---------
template<int CH, int DOGELU>
__global__ void gemv_kernel(const float* __restrict__ x, const float* __restrict__ W,
                            const float* __restrict__ bias, float* __restrict__ out,
                            int M, int N, float* zbuf, int zn){
    PDL_PROLOG;
    __shared__ __align__(16) float xs[8*CH];
    int tid = threadIdx.x;
    int e0 = blockIdx.y * CH;
    if (zbuf){
        int nb = gridDim.x*gridDim.y;
        for (int i = (blockIdx.y*gridDim.x + blockIdx.x)*256 + tid; i < zn; i += nb*256)
            zbuf[i] = 0.f;
    }
    for (int i = tid; i < 8*CH; i += 256){
        int b2 = i / CH, e = i - b2*CH;
        float v = x[b2*M + e0 + e];
        if (DOGELU) v = 0.5f*v*(1.0f + erff(v*0.70710678118654752f));
        xs[b2*CH + e] = v;
    }
    __syncthreads();
    int j = (blockIdx.x*256 + tid)*4;
    if (j >= N) return;
    float4 acc[8];
    #pragma unroll
    for (int b2 = 0; b2 < 8; b2++) acc[b2] = make_float4(0.f,0.f,0.f,0.f);
    const float* Wp = W + (size_t)e0*N + j;
    #pragma unroll
    for (int e = 0; e < CH; e++){
        float4 w4 = *(const float4*)(Wp + (size_t)e*N);
        #pragma unroll
        for (int b2 = 0; b2 < 8; b2++){
            float xv = xs[b2*CH + e];
            acc[b2].x = fmaf(xv,w4.x,acc[b2].x); acc[b2].y = fmaf(xv,w4.y,acc[b2].y);
            acc[b2].z = fmaf(xv,w4.z,acc[b2].z); acc[b2].w = fmaf(xv,w4.w,acc[b2].w);
        }
    }
    if (blockIdx.y == 0){
        float4 bv = *(const float4*)(bias + j);
        #pragma unroll
        for (int b2 = 0; b2 < 8; b2++){
            acc[b2].x += bv.x; acc[b2].y += bv.y; acc[b2].z += bv.z; acc[b2].w += bv.w;
        }
    }
    #pragma unroll
    for (int b2 = 0; b2 < 8; b2++){
        float* p = out + (size_t)b2*N + j;
        atomicAdd(p+0,acc[b2].x); atomicAdd(p+1,acc[b2].y);
        atomicAdd(p+2,acc[b2].z); atomicAdd(p+3,acc[b2].w);
    }
}

// ---------------- K+V copy into new_kv + attention scores; zero hbuf -----------
__global__ void attn_kv_kernel(const float* __restrict__ kv, const float* __restrict__ abias,
                               const int* __restrict__ mask, float* __restrict__ nkv, int l){
    PDL_PROLOG;
    int b = blockIdx.x, sc = blockIdx.y;
    int tid = threadIdx.x, warp = tid >> 5, lane = tid & 31;
    {
        for (int i = (b*128 + sc)*256 + tid; i < NB*NFF; i += NB*128*256) g_hbuf[i] = 0.f;
    }
    __shared__ __align__(16) float qs[NE];
    for (int i = tid; i < NE; i += 256) qs[i] = g_qkv[b*NE3 + i];
    __syncthreads();
    int lp = g_lp[b];
    const float* kc = kv + ((size_t)(l*2+0)*NB + b)*(size_t)NS*NE;
    const float* vc = kv + ((size_t)(l*2+1)*NB + b)*(size_t)NS*NE;
    float* ko = nkv ? nkv + ((size_t)(l*2+0)*NB + b)*(size_t)NS1*NE : nullptr;
    float* vo = nkv ? nkv + ((size_t)(l*2+1)*NB + b)*(size_t)NS1*NE : nullptr;
    int s = sc*8 + warp;
    bool isnew = (s == lp);
    bool iszero = (s == NS) && !isnew;
    const float* ksrc = isnew ? (g_qkv + b*NE3 + NE)   : (kc + (size_t)s*NE);
    const float* vsrc = isnew ? (g_qkv + b*NE3 + 2*NE) : (vc + (size_t)s*NE);
    float4 k4[6], v4[6];
    #pragma unroll
    for (int c = 0; c < 6; c++){
        int e = c*128 + lane*4;
        if (iszero){ k4[c] = make_float4(0.f,0.f,0.f,0.f); v4[c] = k4[c]; }
        else { k4[c] = *(const float4*)(ksrc + e); v4[c] = *(const float4*)(vsrc + e); }
    }
    if (ko){
        #pragma unroll
        for (int c = 0; c < 6; c++){
            int e = c*128 + lane*4;
            __stcs((float4*)(ko + (size_t)s*NE + e), k4[c]);     // K never re-read
            *(float4*)(vo + (size_t)s*NE + e) = v4[c];           // V re-read by attn_sv
        }
    }
    float part[6];
    #pragma unroll
    for (int c = 0; c < 6; c++){
        int e = c*128 + lane*4;
        part[c] = k4[c].x*qs[e] + k4[c].y*qs[e+1] + k4[c].z*qs[e+2] + k4[c].w*qs[e+3];
    }
    #pragma unroll
    for (int c = 0; c < 6; c++){
        float p = part[c];
        p += __shfl_xor_sync(0xffffffffu, p, 8);
        p += __shfl_xor_sync(0xffffffffu, p, 4);
        p += __shfl_xor_sync(0xffffffffu, p, 2);
        p += __shfl_xor_sync(0xffffffffu, p, 1);
        part[c] = p;
    }
    if ((lane & 15) == 0){
        int hb = lane >> 4;
        bool msk = (mask[b*NS1 + s] == 0);
        float ab = abias[s];
        #pragma unroll
        for (int c = 0; c < 6; c++){
            int h = 2*c + hb;
            g_scores[(b*NH + h)*NS1 + s] = msk ? -1e9f : (part[c]*0.125f + ab);
        }
    }
}

// ---------------- softmax + weighted-V -----------------------------------------
// grid (B, H, 16) x 256: block = one (b,h) x 64-row chunk; redundant softmax.
// Each thread: 16 rows of one head-dim column (4 row-phases x 16 unrolled).
__global__ void attn_sv_kernel(const float* __restrict__ kv, const float* __restrict__ nkv, int l){
    PDL_PROLOG;
    int b = blockIdx.x, h = blockIdx.y, ck = blockIdx.z;
    int tid = threadIdx.x;
    __shared__ float sm[NS1];
    __shared__ float red[8];
    const float* sr = g_scores + ((size_t)b*NH + h)*NS1;
    float v[4]; float m = -1e30f;
    #pragma unroll
    for (int k = 0; k < 4; k++){ v[k] = sr[tid + k*256]; m = fmaxf(m, v[k]); }
    #pragma unroll
    for (int o = 16; o; o >>= 1) m = fmaxf(m, __shfl_xor_sync(0xffffffffu, m, o));
    if ((tid & 31) == 0) red[tid >> 5] = m;
    __syncthreads();
    m = red[0];
    #pragma unroll
    for (int w2 = 1; w2 < 8; w2++) m = fmaxf(m, red[w2]);
    float ssum = 0.f;
    #pragma unroll
    for (int k = 0; k < 4; k++){ v[k] = expf(v[k] - m); ssum += v[k]; }
    #pragma unroll
    for (int o = 16; o; o >>= 1) ssum += __shfl_xor_sync(0xffffffffu, ssum, o);
    __syncthreads();
    if ((tid & 31) == 0) red[tid >> 5] = ssum;
    __syncthreads();
    float tot = red[0];
    #pragma unroll
    for (int w2 = 1; w2 < 8; w2++) tot += red[w2];
    float inv = 1.0f/tot;
    #pragma unroll
    for (int k = 0; k < 4; k++) sm[tid + k*256] = v[k]*inv;
    __syncthreads();
    int col = tid & 63, rp = tid >> 6;          // rp in 0..3
    float acc = 0.f;
    if (nkv){
        const float* vo = nkv + ((size_t)(l*2+1)*NB + b)*(size_t)NS1*NE + h*ND + col;
        #pragma unroll
        for (int i = 0; i < 16; i++){
            int s = ck*64 + i*4 + rp;
            acc = fmaf(sm[s], vo[(size_t)s*NE], acc);
        }
    } else {
        int lp = g_lp[b];
        const float* vc = kv + ((size_t)(l*2+1)*NB + b)*(size_t)NS*NE;
        #pragma unroll
        for (int i = 0; i < 16; i++){
            int s = ck*64 + i*4 + rp;
            float vv;
            if (s == lp) vv = g_qkv[b*NE3 + 2*NE + h*ND + col];
            else if (s == NS) vv = 0.f;
            else vv = vc[(size_t)s*NE + h*ND + col];
            acc = fmaf(sm[s], vv, acc);
        }
    }
    __shared__ float cacc[256];
    cacc[tid] = acc; __syncthreads();
    if (tid < 64)
        atomicAdd(&g_ctx[b*NE + h*ND + tid],
                  cacc[tid] + cacc[tid+64] + cacc[tid+128] + cacc[tid+192]);
}

// ---------------- lm head with fused final layernorm ---------------------------
__global__ void lm_kernel(const float* __restrict__ wte, const float* __restrict__ lnfw,
                          const float* __restrict__ lnfb){
    PDL_PROLOG;
    __shared__ __align__(16) float xs[NB*NE];
    int tid = threadIdx.x;
    int warp = tid >> 5, lane = tid & 31;
    {   // redundant LN of row `warp` (8 warps = 8 batch rows)
        const float* x = g_states + warp*NE;
        float s = 0.f;
        for (int i = lane; i < NE; i += 32) s += x[i];
        #pragma unroll
        for (int o = 16; o; o >>= 1) s += __shfl_xor_sync(0xffffffffu, s, o);
        float mean = s*(1.0f/NE);
        float v = 0.f;
        for (int i = lane; i < NE; i += 32){ float d = x[i]-mean; v += d*d; }
        #pragma unroll
        for (int o = 16; o; o >>= 1) v += __shfl_xor_sync(0xffffffffu, v, o);
        float rs = rsqrtf(v*(1.0f/NE) + 1e-5f);
        for (int i = lane; i < NE; i += 32)
            xs[warp*NE + i] = (x[i]-mean)*rs*lnfw[i] + lnfb[i];
    }
    __syncthreads();
    long long t0 = (long long)blockIdx.x*16 + warp*2;
    if (t0 >= NV) return;
    bool has1 = (t0 + 1 < NV);
    const float* r0 = wte + (size_t)t0*NE;
    const float* r1 = has1 ? wte + (size_t)(t0+1)*NE : r0;
    float acc[16];
    #pragma unroll
    for (int i = 0; i < 16; i++) acc[i] = 0.f;
    #pragma unroll
    for (int c = 0; c < 6; c++){
        int e = c*128 + lane*4;
        float4 w0 = *(const float4*)(r0 + e);
        float4 w1 = *(const float4*)(r1 + e);
        #pragma unroll
        for (int b2 = 0; b2 < 8; b2++){
            float4 x4 = *(const float4*)&xs[b2*NE + e];
            acc[b2]   = fmaf(w0.x,x4.x, fmaf(w0.y,x4.y, fmaf(w0.z,x4.z, fmaf(w0.w,x4.w, acc[b2]))));
            acc[8+b2] = fmaf(w1.x,x4.x, fmaf(w1.y,x4.y, fmaf(w1.z,x4.z, fmaf(w1.w,x4.w, acc[8+b2]))));
        }
    }
    #pragma unroll
    for (int i = 0; i < 16; i++){
        float p = acc[i];
        p += __shfl_xor_sync(0xffffffffu, p, 16);
        p += __shfl_xor_sync(0xffffffffu, p, 8);
        p += __shfl_xor_sync(0xffffffffu, p, 4);
        p += __shfl_xor_sync(0xffffffffu, p, 2);
        p += __shfl_xor_sync(0xffffffffu, p, 1);
        acc[i] = p;
    }
    if (lane < 8){
        g_logits[(size_t)lane*NV + t0] = acc[lane];
        if (has1) g_logits[(size_t)lane*NV + t0 + 1] = acc[8 + lane];
    }
}

// ---------------- vocab softmax + argmax (ILP-4 loops) -------------------------
__global__ void finish_kernel(float* __restrict__ probs, float* __restrict__ chosen_f,
                              int* __restrict__ chosen_i){
    PDL_PROLOG;
    int b = blockIdx.x, tid = threadIdx.x;
    __shared__ float rv[1024];
    __shared__ int   ri[1024];
    const float* lg = g_logits + (size_t)b*NV;
    float m = -1e30f; int mi = 0;
    // 50257 = 49 * 1024 + 81; ILP-4 over stride-1024 groups
    for (int t = tid; t < NV; t += 4096){
        float v0 = lg[t];
        float v1 = (t+1024 < NV) ? lg[t+1024] : -1e30f;
        float v2 = (t+2048 < NV) ? lg[t+2048] : -1e30f;
        float v3 = (t+3072 < NV) ? lg[t+3072] : -1e30f;
        if (v0 > m){ m = v0; mi = t; }
        if (v1 > m){ m = v1; mi = t+1024; }
        if (v2 > m){ m = v2; mi = t+2048; }
        if (v3 > m){ m = v3; mi = t+3072; }
    }
    rv[tid] = m; ri[tid] = mi; __syncthreads();
    for (int o = 512; o; o >>= 1){
        if (tid < o){
            if (rv[tid+o] > rv[tid] || (rv[tid+o] == rv[tid] && ri[tid+o] < ri[tid])){
                rv[tid] = rv[tid+o]; ri[tid] = ri[tid+o];
            }
        }
        __syncthreads();
    }
    float mx = rv[0]; int am = ri[0]; __syncthreads();
    float s = 0.f;
    for (int t = tid; t < NV; t += 4096){
        float v0 = lg[t];
        float v1 = (t+1024 < NV) ? lg[t+1024] : 0.f;
        float v2 = (t+2048 < NV) ? lg[t+2048] : 0.f;
        float v3 = (t+3072 < NV) ? lg[t+3072] : 0.f;
        float e0 = expf(v0-mx);
        float e1 = (t+1024 < NV) ? expf(v1-mx) : 0.f;
        float e2 = (t+2048 < NV) ? expf(v2-mx) : 0.f;
        float e3 = (t+3072 < NV) ? expf(v3-mx) : 0.f;
        s += (e0+e1)+(e2+e3);
        if (probs){
            probs[(size_t)b*NV + t] = e0;
            if (t+1024 < NV) probs[(size_t)b*NV + t+1024] = e1;
            if (t+2048 < NV) probs[(size_t)b*NV + t+2048] = e2;
            if (t+3072 < NV) probs[(size_t)b*NV + t+3072] = e3;
        }
    }
    rv[tid] = s; __syncthreads();
    for (int o = 512; o; o >>= 1){ if (tid < o) rv[tid] += rv[tid+o]; __syncthreads(); }
    float inv = 1.0f/rv[0];
    if (probs){
        float* pb = probs + (size_t)b*NV;
        for (int t = tid; t < NV; t += 4096){
            float p0 = pb[t];
            float p1 = (t+1024 < NV) ? pb[t+1024] : 0.f;
            float p2 = (t+2048 < NV) ? pb[t+2048] : 0.f;
            float p3 = (t+3072 < NV) ? pb[t+3072] : 0.f;
            pb[t] = p0*inv;
            if (t+1024 < NV) pb[t+1024] = p1*inv;
            if (t+2048 < NV) pb[t+2048] = p2*inv;
            if (t+3072 < NV) pb[t+3072] = p3*inv;
        }
    }
    if (tid == 0){
        if (chosen_f) chosen_f[b] = (float)am;
        if (chosen_i) chosen_i[b] = am;
    }
}

// ---------------- PDL launch helper ---------------------------------------------
template <typename... ExpTypes, typename... ActTypes>
static inline void pdl_launch(void (*kern)(ExpTypes...), dim3 grid, dim3 block,
                              ActTypes... args){
    cudaLaunchConfig_t cfg = {};
    cfg.gridDim = grid;
    cfg.blockDim = block;
    cfg.dynamicSmemBytes = 0;
    cfg.stream = 0;
    cudaLaunchAttribute at[1];
    at[0].id = cudaLaunchAttributeProgrammaticStreamSerialization;
    at[0].val.programmaticStreamSerializationAllowed = 1;
    cfg.attrs = at;
    cfg.numAttrs = 1;
    cudaLaunchKernelEx(&cfg, kern, (ExpTypes)args...);
}

// ---------------- launch --------------------------------------------------------
extern "C" void kernel_launch(void* const* d_in, const int* in_sizes, int n_in,
                              void* d_out, int out_size){
    const int*   ids  = (const int*)  d_in[0];
    const int*   mask = (const int*)  d_in[1];
    const float* kv   = (const float*)d_in[2];
    const float* wte  = (const float*)d_in[3];
    const float* wpe  = (const float*)d_in[4];
    const float* ln1w = (const float*)d_in[5];
    const float* ln1b = (const float*)d_in[6];
    const float* caw  = (const float*)d_in[7];
    const float* cab  = (const float*)d_in[8];
    const float* ab   = (const float*)d_in[9];
    const float* cpw  = (const float*)d_in[10];
    const float* cpb  = (const float*)d_in[11];
    const float* ln2w = (const float*)d_in[12];
    const float* ln2b = (const float*)d_in[13];
    const float* fcw  = (const float*)d_in[14];
    const float* fcb  = (const float*)d_in[15];
    const float* prw  = (const float*)d_in[16];
    const float* prb  = (const float*)d_in[17];
    const float* lnfw = (const float*)d_in[18];
    const float* lnfb = (const float*)d_in[19];

    float *st, *qkvp, *ctxp, *hb;
    cudaGetSymbolAddress((void**)&st,   g_states);
    cudaGetSymbolAddress((void**)&qkvp, g_qkv);
    cudaGetSymbolAddress((void**)&ctxp, g_ctx);
    cudaGetSymbolAddress((void**)&hb,   g_hbuf);

    long long nkvN  = (long long)NL*2*NB*NS1*NE;                  // 150,994,944
    long long fullN = (long long)NB + (long long)NB*NV + nkvN;    // 151,397,008
    float* outf = (float*)d_out;
    float* chosen_f = nullptr; int* chosen_i = nullptr;
    float* probs = nullptr; float* nkv = nullptr;
    long long osz = (long long)out_size;
    if (osz == fullN){ chosen_f = outf; probs = outf + NB; nkv = outf + NB + (long long)NB*NV; }
    else if (osz == nkvN){ nkv = outf; }
    else if (osz == (long long)NB*NV){ probs = outf; }
    else if (osz == (long long)NB){ chosen_i = (int*)d_out; }
    else if (osz == (long long)NB + (long long)NB*NV){ chosen_f = outf; probs = outf + NB; }
    else {
        chosen_f = outf;
        if (osz >= (long long)NB + (long long)NB*NV) probs = outf + NB;
        if (osz >= fullN) nkv = outf + NB + (long long)NB*NV;
    }

    pdl_launch(embed_kernel, dim3(NB), dim3(256), ids, mask, wte, wpe);
    for (int l = 0; l < NL; l++){
        pdl_launch(gemv_ln_kernel<16>, dim3(3,48), dim3(256),
                   ln1w + l*NE, ln1b + l*NE,
                   caw + (size_t)l*NE*NE3, cab + (size_t)l*NE3, qkvp, NE3);
        pdl_launch(attn_kv_kernel, dim3(NB,128), dim3(256),
                   kv, ab + (size_t)l*NS1, mask, nkv, l);
        pdl_launch(attn_sv_kernel, dim3(NB,NH,16), dim3(256), kv, (const float*)nkv, l);
        pdl_launch(gemv_kernel<16,0>, dim3(1,48), dim3(256),
                   (const float*)ctxp, cpw + (size_t)l*NE*NE, cpb + (size_t)l*NE,
                   st, NE, NE, qkvp, NB*NE3);
        pdl_launch(gemv_ln_kernel<16>, dim3(3,48), dim3(256),
                   ln2w + l*NE, ln2b + l*NE,
                   fcw + (size_t)l*NE*NFF, fcb + (size_t)l*NFF, hb, NFF);
        pdl_launch(gemv_kernel<24,1>, dim3(1,128), dim3(256),
                   (const float*)hb, prw + (size_t)l*NFF*NE, prb + (size_t)l*NE,
                   st, NFF, NE, ctxp, NB*NE);
    }
    pdl_launch(lm_kernel, dim3((NV + 15)/16), dim3(256), wte, lnfw, lnfb);
    pdl_launch(finish_kernel, dim3(NB), dim3(1024), probs, chosen_f, chosen_i);
}